// round 12
// baseline (speedup 1.0000x reference)
#include <cuda_runtime.h>
#include <cuda_bf16.h>
#include <cstdint>
#include <cstddef>

#define B_    32768
#define T_    3
#define D_    64
#define H_    32
#define NBLK  128   // B_/256

// ---------------- scratch (device globals: allocation-free) ----------------
__device__ unsigned long long g_xg[(size_t)T_ * 128 * B_]; // xg pairs [t][j/2][r]
__device__ float g_ps1[T_ * NBLK * H_];
__device__ float g_pq1[T_ * NBLK * H_];
__device__ float g_ps2[T_ * NBLK * H_];
__device__ float g_pq2[T_ * NBLK * H_];
__device__ float2 g_bn1[T_ * H_];   // (scale, shift)
__device__ float2 g_bn2[T_ * H_];
__device__ int g_c1, g_c2, g_c3;    // barrier counters (self-resetting)
__device__ int g_f1, g_f2;          // ready flags (self-resetting)
// weight tiles: 6 x [256 n][64 k] bf16, 128B rows, SW128-swizzled
// 0 = Whh_hi, 1 = Whh_lo, 2 = (Wih+Whh)_hi, 3 = (Wih+Whh)_lo, 4 = Wih_hi, 5 = Wih_lo
__device__ __align__(16) uint8_t g_wt[6 * 32768];

#define UNPK(v, lo, hi) do { unsigned _l, _h; \
    asm("mov.b64 {%0,%1}, %2;" : "=r"(_l), "=r"(_h) : "l"(v)); \
    lo = __uint_as_float(_l); hi = __uint_as_float(_h); } while (0)
#define PK64(lo, hi, v) asm("mov.b64 %0, {%1,%2};" : "=l"(v) : "r"(__float_as_uint(lo)), "r"(__float_as_uint(hi)))

__device__ __forceinline__ float ex2f(float x) {
    float r; asm("ex2.approx.ftz.f32 %0, %1;" : "=f"(r) : "f"(x)); return r;
}
__device__ __forceinline__ float rcpf(float x) {
    float r; asm("rcp.approx.ftz.f32 %0, %1;" : "=f"(r) : "f"(x)); return r;
}
// L1-bypassing, hoist-proof load for in-kernel-produced global data
__device__ __forceinline__ float2 ldcg2(const float2* p) {
    float2 v;
    asm volatile("ld.global.cg.v2.f32 {%0,%1}, [%2];" : "=f"(v.x), "=f"(v.y) : "l"(p));
    return v;
}
// paired LSTM cells: shares RCPs between the two cells. 12 MUFU / pair.
__device__ __forceinline__ void lstm_cell2(float gi0, float gf0, float gg0, float go0,
                                           float gi1, float gf1, float gg1, float go1,
                                           float& c0, float& c1, float& h0, float& h1) {
    const float L2E = 1.4426950408889634f;
    float a0 = ex2f(-L2E * gf0), u0 = ex2f(-L2E * gi0), b0 = ex2f(-2.f * L2E * gg0);
    float a1 = ex2f(-L2E * gf1), u1 = ex2f(-L2E * gi1), b1 = ex2f(-2.f * L2E * gg1);
    float pa0 = 1.f + a0, t0 = (1.f + u0) * (1.f + b0);
    float pa1 = 1.f + a1, t1 = (1.f + u1) * (1.f + b1);
    float D0 = pa0 * t0, N0 = c0 * t0 + (1.f - b0) * pa0;
    float D1 = pa1 * t1, N1 = c1 * t1 + (1.f - b1) * pa1;
    float r = rcpf(D0 * D1);
    float cn0 = N0 * (r * D1), cn1 = N1 * (r * D0);
    float v0 = ex2f(-L2E * go0), w0 = ex2f(-2.f * L2E * cn0);
    float v1 = ex2f(-L2E * go1), w1 = ex2f(-2.f * L2E * cn1);
    float P0 = (1.f + v0) * (1.f + w0), P1 = (1.f + v1) * (1.f + w1);
    float r2 = rcpf(P0 * P1);
    c0 = cn0; c1 = cn1;
    h0 = (1.f - w0) * (r2 * P1);
    h1 = (1.f - w1) * (r2 * P0);
}
__host__ __device__ __forceinline__ uint32_t swz128(uint32_t o) {
    return o ^ ((o >> 3) & 0x70);
}
__device__ __forceinline__ uint32_t pack_bf16(float lo, float hi) {
    uint32_t r;
    asm("cvt.rn.bf16x2.f32 %0, %1, %2;" : "=r"(r) : "f"(hi), "f"(lo));
    return r;
}

// ---------------- HMMA helpers ----------------
__device__ __forceinline__ void mma_bf16(float d[4], const uint32_t a[4],
                                         uint32_t b0, uint32_t b1) {
    asm volatile(
        "mma.sync.aligned.m16n8k16.row.col.f32.bf16.bf16.f32 "
        "{%0,%1,%2,%3}, {%4,%5,%6,%7}, {%8,%9}, {%0,%1,%2,%3};"
        : "+f"(d[0]), "+f"(d[1]), "+f"(d[2]), "+f"(d[3])
        : "r"(a[0]), "r"(a[1]), "r"(a[2]), "r"(a[3]), "r"(b0), "r"(b1));
}
__device__ __forceinline__ void ldsm4(uint32_t r[4], uint32_t addr) {
    asm volatile("ldmatrix.sync.aligned.m8n8.x4.shared.b16 {%0,%1,%2,%3}, [%4];"
                 : "=r"(r[0]), "=r"(r[1]), "=r"(r[2]), "=r"(r[3]) : "r"(addr) : "memory");
}

// ================= persistent fused MLP: grid 128 x 256 =================
#define F_AHI  0u
#define F_ALO  32768u
#define F_WIH  65536u
#define F_SW1  131072u
#define F_SW2  139264u
#define F_SW3  143360u
#define F_SB   151552u
#define F_SR0  152576u
#define F_SR1  153600u
#define F_SMEM 154624

__global__ void __launch_bounds__(256) k_mlp_fused(
        const float* __restrict__ x,
        const float* __restrict__ W1, const float* __restrict__ b1,
        const float* __restrict__ g1, const float* __restrict__ be1,
        const float* __restrict__ W2, const float* __restrict__ b2,
        const float* __restrict__ g2, const float* __restrict__ be2,
        const float* __restrict__ W3, const float* __restrict__ b3,
        const float* __restrict__ Wih, const float* __restrict__ Whh,
        const float* __restrict__ bih, const float* __restrict__ bhh) {
    extern __shared__ __align__(16) uint8_t sm[];
    uint32_t smem_base;
    asm("{ .reg .u64 t; cvta.to.shared.u64 t, %1; cvt.u32.u64 %0, t; }"
        : "=r"(smem_base) : "l"(sm));
    float* sacc = (float*)(sm);
    float* sW1 = (float*)(sm + F_SW1);
    float* sW2 = (float*)(sm + F_SW2);
    float* sW3 = (float*)(sm + F_SW3);
    float* sb  = (float*)(sm + F_SB);
    float* sr0 = (float*)(sm + F_SR0);
    float* sr1 = (float*)(sm + F_SR1);
    __shared__ int sflag;
    const int tid = threadIdx.x, bid = blockIdx.x;
    const int wid = tid >> 5, lane = tid & 31;
    const int part = tid >> 5, ch = tid & 31;

    for (int i = tid; i < 2048; i += 256) { int j = i >> 6, k = i & 63; sW1[k * 32 + j] = W1[i]; }
    for (int i = tid; i < 1024; i += 256) { int j = i >> 5, k = i & 31; sW2[k * 32 + j] = W2[i]; }
    for (int i = tid; i < 2048; i += 256) { int j = i >> 5, k = i & 31; sW3[k * 64 + j] = W3[i]; }
    sb[tid] = bih[tid] + bhh[tid];

    // ---------- stage 1: a1 = x @ W1^T + b1 (kept in regs), partial stats ----------
    float aT[3][32];
#pragma unroll
    for (int t = 0; t < T_; t++) {
        const size_t r = (size_t)bid * 256 + tid;
        float xr[64];
        const float4* xp = (const float4*)(x + ((size_t)t * B_ + r) * D_);
#pragma unroll
        for (int i = 0; i < 16; i++) {
            float4 v = xp[i];
            xr[4*i] = v.x; xr[4*i+1] = v.y; xr[4*i+2] = v.z; xr[4*i+3] = v.w;
        }
        float acc[32];
#pragma unroll
        for (int j = 0; j < 32; j++) acc[j] = __ldg(&b1[j]);
        __syncthreads();   // sW1 ready (first t) / sacc & sr reusable (later t)
#pragma unroll
        for (int k = 0; k < 64; k++) {
            float xk = xr[k];
#pragma unroll
            for (int q = 0; q < 8; q++) {
                float4 w = *(const float4*)&sW1[k * 32 + q * 4];
                acc[q*4+0] = fmaf(w.x, xk, acc[q*4+0]);
                acc[q*4+1] = fmaf(w.y, xk, acc[q*4+1]);
                acc[q*4+2] = fmaf(w.z, xk, acc[q*4+2]);
                acc[q*4+3] = fmaf(w.w, xk, acc[q*4+3]);
            }
        }
#pragma unroll
        for (int j = 0; j < 32; j++) { aT[t][j] = acc[j]; sacc[tid * 33 + j] = acc[j]; }
        __syncthreads();
        {
            float s = 0.f, q = 0.f;
#pragma unroll
            for (int rr = 0; rr < 32; rr++) {
                float v = sacc[(part * 32 + rr) * 33 + ch];
                s += v; q = fmaf(v, v, q);
            }
            sr0[part * 32 + ch] = s;
            sr1[part * 32 + ch] = q;
        }
        __syncthreads();
        if (tid < 32) {
            float s = 0.f, q = 0.f;
#pragma unroll
            for (int p = 0; p < 8; p++) { s += sr0[p * 32 + tid]; q += sr1[p * 32 + tid]; }
            g_ps1[(t * NBLK + bid) * 32 + tid] = s;
            g_pq1[(t * NBLK + bid) * 32 + tid] = q;
        }
    }

    // fused weight prep (bf16 hi/lo splits), blocks 0..63
    if (bid < 64) {
        int idx = bid * 256 + tid;   // < 16384
        int n = idx >> 6, k = idx & 63;
        float whh = Whh[idx];
        float wih = Wih[idx];
        float ws = whh + wih;
        __nv_bfloat16 hh = __float2bfloat16_rn(whh);
        __nv_bfloat16 hl = __float2bfloat16_rn(whh - __bfloat162float(hh));
        __nv_bfloat16 sh = __float2bfloat16_rn(ws);
        __nv_bfloat16 sl = __float2bfloat16_rn(ws - __bfloat162float(sh));
        __nv_bfloat16 ih = __float2bfloat16_rn(wih);
        __nv_bfloat16 il = __float2bfloat16_rn(wih - __bfloat162float(ih));
        uint32_t off = swz128((uint32_t)(n * 128 + k * 2));
        *(__nv_bfloat16*)(g_wt + 0 * 32768 + off) = hh;
        *(__nv_bfloat16*)(g_wt + 1 * 32768 + off) = hl;
        *(__nv_bfloat16*)(g_wt + 2 * 32768 + off) = sh;
        *(__nv_bfloat16*)(g_wt + 3 * 32768 + off) = sl;
        *(__nv_bfloat16*)(g_wt + 4 * 32768 + off) = ih;
        *(__nv_bfloat16*)(g_wt + 5 * 32768 + off) = il;
    }

    // ---------- barrier 1: BN1 stats ----------
    __threadfence();
    if (tid == 0) sflag = (atomicAdd(&g_c1, 1) == NBLK - 1);
    __syncthreads();
    if (sflag) {
        __threadfence();
        if (tid < 96) {
            int t = tid >> 5, c2 = tid & 31;
            float s = 0.f, q = 0.f;
            for (int b = 0; b < NBLK; b++) {
                s += g_ps1[(t * NBLK + b) * 32 + c2];
                q += g_pq1[(t * NBLK + b) * 32 + c2];
            }
            float m = s * (1.f / B_);
            float v = q * (1.f / B_) - m * m;
            float sc = g1[c2] * rsqrtf(v + 1e-5f);
            g_bn1[tid] = make_float2(sc, be1[c2] - m * sc);
        }
        __syncthreads();
        if (tid == 0) { __threadfence(); g_c1 = 0; atomicExch(&g_f1, 1); }
    }
    if (tid == 0) {
        while (atomicAdd(&g_f1, 0) == 0) __nanosleep(128);
        __threadfence();   // acquire
    }
    __syncthreads();

    // copy Wih HMMA tiles (prep complete by barrier 1)
    {
        const uint4* src = (const uint4*)(g_wt + 4 * 32768);
        uint4* dst = (uint4*)(sm + F_WIH);
        for (int i = tid; i < 65536 / 16; i += 256) dst[i] = src[i];
    }

    // ---------- stage 2: a2 = relu(BN1(a1)) @ W2^T + b2, partial stats ----------
#pragma unroll
    for (int t = 0; t < T_; t++) {
        float a[32];
#pragma unroll
        for (int j = 0; j < 32; j++) {
            float2 s0 = ldcg2(&g_bn1[t * 32 + j]);
            a[j] = fmaxf(0.f, fmaf(aT[t][j], s0.x, s0.y));
        }
        float acc[32];
#pragma unroll
        for (int j = 0; j < 32; j++) acc[j] = __ldg(&b2[j]);
#pragma unroll
        for (int k = 0; k < 32; k++) {
            float ak = a[k];
#pragma unroll
            for (int q = 0; q < 8; q++) {
                float4 w = *(const float4*)&sW2[k * 32 + q * 4];
                acc[q*4+0] = fmaf(w.x, ak, acc[q*4+0]);
                acc[q*4+1] = fmaf(w.y, ak, acc[q*4+1]);
                acc[q*4+2] = fmaf(w.z, ak, acc[q*4+2]);
                acc[q*4+3] = fmaf(w.w, ak, acc[q*4+3]);
            }
        }
        __syncthreads();
#pragma unroll
        for (int j = 0; j < 32; j++) { aT[t][j] = acc[j]; sacc[tid * 33 + j] = acc[j]; }
        __syncthreads();
        {
            float s = 0.f, q = 0.f;
#pragma unroll
            for (int rr = 0; rr < 32; rr++) {
                float v = sacc[(part * 32 + rr) * 33 + ch];
                s += v; q = fmaf(v, v, q);
            }
            sr0[part * 32 + ch] = s;
            sr1[part * 32 + ch] = q;
        }
        __syncthreads();
        if (tid < 32) {
            float s = 0.f, q = 0.f;
#pragma unroll
            for (int p = 0; p < 8; p++) { s += sr0[p * 32 + tid]; q += sr1[p * 32 + tid]; }
            g_ps2[(t * NBLK + bid) * 32 + tid] = s;
            g_pq2[(t * NBLK + bid) * 32 + tid] = q;
        }
    }

    // ---------- barrier 2: BN2 stats ----------
    __threadfence();
    if (tid == 0) sflag = (atomicAdd(&g_c2, 1) == NBLK - 1);
    __syncthreads();
    if (sflag) {
        __threadfence();
        if (tid < 96) {
            int t = tid >> 5, c2 = tid & 31;
            float s = 0.f, q = 0.f;
            for (int b = 0; b < NBLK; b++) {
                s += g_ps2[(t * NBLK + b) * 32 + c2];
                q += g_pq2[(t * NBLK + b) * 32 + c2];
            }
            float m = s * (1.f / B_);
            float v = q * (1.f / B_) - m * m;
            float sc = g2[c2] * rsqrtf(v + 1e-5f);
            g_bn2[tid] = make_float2(sc, be2[c2] - m * sc);
        }
        __syncthreads();
        if (tid == 0) { __threadfence(); g_c2 = 0; atomicExch(&g_f2, 1); }
    }
    if (tid == 0) {
        while (atomicAdd(&g_f2, 0) == 0) __nanosleep(128);
        __threadfence();   // acquire
    }
    __syncthreads();

    // ---------- stage 3: enc = relu(BN2(a2)) @ W3^T + b3 ; xg = enc @ Wih^T + bsum ----------
    const int l7 = lane & 7;
    const uint32_t lxor = (uint32_t)l7 * 16u;
    const uint32_t aoff16 = (uint32_t)((lane >> 4) & 1) * 16u;
    const uint32_t boff16 = (uint32_t)((lane >> 3) & 1) * 16u;
    const uint32_t arow0 = (uint32_t)(wid * 32 + l7 + ((lane >> 3) & 1) * 8) * 128u;
    const uint32_t brow_l = (uint32_t)(((lane >> 4) & 1) * 8 + l7) * 128u;
    const int qr = lane >> 2, qc = lane & 3;
    const size_t rowG0 = (size_t)bid * 256 + wid * 32 + qr;
    const uint32_t aHi = smem_base + F_AHI, aLo = smem_base + F_ALO;
    const uint32_t whi = smem_base + F_WIH;

#pragma unroll
    for (int t = 0; t < T_; t++) {
        float e[64];
#pragma unroll
        for (int j = 0; j < 64; j++) e[j] = __ldg(&b3[j]);
#pragma unroll
        for (int k = 0; k < 32; k++) {
            float2 s0 = ldcg2(&g_bn2[t * 32 + k]);
            float ak = fmaxf(0.f, fmaf(aT[t][k], s0.x, s0.y));
#pragma unroll
            for (int q = 0; q < 16; q++) {
                float4 w = *(const float4*)&sW3[k * 64 + q * 4];
                e[q*4+0] = fmaf(w.x, ak, e[q*4+0]);
                e[q*4+1] = fmaf(w.y, ak, e[q*4+1]);
                e[q*4+2] = fmaf(w.z, ak, e[q*4+2]);
                e[q*4+3] = fmaf(w.w, ak, e[q*4+3]);
            }
        }
        {
            const uint32_t rb = (uint32_t)tid * 128u;
            const uint32_t rx = (uint32_t)(tid & 7) * 16u;
#pragma unroll
            for (int q = 0; q < 8; q++) {
                uint32_t off = rb + (((uint32_t)q * 16u) ^ rx);
                uint32_t ph[4], pl[4];
#pragma unroll
                for (int j = 0; j < 4; j++) {
                    float e0 = e[q*8 + 2*j], e1 = e[q*8 + 2*j + 1];
                    uint32_t p = pack_bf16(e0, e1);
                    ph[j] = p;
                    pl[j] = pack_bf16(e0 - __uint_as_float(p << 16),
                                      e1 - __uint_as_float(p & 0xffff0000u));
                }
                *(uint4*)(sm + F_AHI + off) = make_uint4(ph[0], ph[1], ph[2], ph[3]);
                *(uint4*)(sm + F_ALO + off) = make_uint4(pl[0], pl[1], pl[2], pl[3]);
            }
        }
        __syncwarp();

        unsigned long long* xgt = g_xg + (size_t)t * 128 * B_;
#pragma unroll
        for (int cd = 0; cd < 4; cd++) {
            float acc[2][4][2][4];
#pragma unroll
            for (int mt = 0; mt < 2; mt++)
#pragma unroll
                for (int g = 0; g < 4; g++)
#pragma unroll
                    for (int ds = 0; ds < 2; ds++)
#pragma unroll
                        for (int z = 0; z < 4; z++) acc[mt][g][ds][z] = 0.f;
            const uint32_t brow_cd = (uint32_t)(cd * 16) * 128u + brow_l;
#pragma unroll
            for (int kt = 0; kt < 4; kt++) {
                const uint32_t acol = ((uint32_t)(kt * 32) + aoff16) ^ lxor;
                const uint32_t bcol = ((uint32_t)(kt * 32) + boff16) ^ lxor;
                uint32_t ah[2][4], al[2][4];
                ldsm4(ah[0], aHi + arow0 + acol);
                ldsm4(ah[1], aHi + arow0 + 2048u + acol);
                ldsm4(al[0], aLo + arow0 + acol);
                ldsm4(al[1], aLo + arow0 + 2048u + acol);
                uint32_t bh[4][4], bl[4][4];
#pragma unroll
                for (int g = 0; g < 4; g++) {
                    ldsm4(bh[g], whi + (uint32_t)g * 8192u + brow_cd + bcol);
                    ldsm4(bl[g], whi + 32768u + (uint32_t)g * 8192u + brow_cd + bcol);
                }
#pragma unroll
                for (int mt = 0; mt < 2; mt++)
#pragma unroll
                    for (int g = 0; g < 4; g++)
#pragma unroll
                        for (int ds = 0; ds < 2; ds++) {
                            mma_bf16(acc[mt][g][ds], ah[mt], bh[g][ds*2], bh[g][ds*2+1]);
                            mma_bf16(acc[mt][g][ds], al[mt], bh[g][ds*2], bh[g][ds*2+1]);
                            mma_bf16(acc[mt][g][ds], ah[mt], bl[g][ds*2], bl[g][ds*2+1]);
                        }
            }
#pragma unroll
            for (int g = 0; g < 4; g++)
#pragma unroll
                for (int ds = 0; ds < 2; ds++) {
                    const int pi = cd * 8 + ds * 4 + qc;
                    float2 bs = *(const float2*)&sb[g * 64 + 2 * pi];
#pragma unroll
                    for (int mt = 0; mt < 2; mt++)
#pragma unroll
                        for (int rr = 0; rr < 2; rr++) {
                            float v0 = acc[mt][g][ds][rr*2]     + bs.x;
                            float v1 = acc[mt][g][ds][rr*2 + 1] + bs.y;
                            unsigned long long pk;
                            PK64(v0, v1, pk);
                            xgt[(size_t)(g * 32 + pi) * B_ + rowG0 + mt * 16 + rr * 8] = pk;
                        }
                }
        }
        __syncwarp();
    }

    // ---------- end barrier: reset flags for next graph replay ----------
    if (tid == 0) {
        if (atomicAdd(&g_c3, 1) == NBLK - 1) { g_f1 = 0; g_f2 = 0; g_c3 = 0; }
    }
}

// ---------------- stage 4: HMMA 28-step LSTM (round-8 config), grid 148 x 448 ----------------
#define LA_BUF   57344u
#define LA_LO    28672u
#define LW_OFF   114688u
#define LBIAS    180224u
#define LSTM_SMEM 181248

__global__ void __launch_bounds__(448, 1) k_lstm_mm(const float* __restrict__ bih,
                                                    const float* __restrict__ bhh,
                                                    float* __restrict__ out) {
    extern __shared__ __align__(16) uint8_t sm[];
    uint32_t smem_base;
    asm("{ .reg .u64 t; cvta.to.shared.u64 t, %1; cvt.u32.u64 %0, t; }"
        : "=r"(smem_base) : "l"(sm));
    float* sbsum = (float*)(sm + LBIAS);
    const int tid = threadIdx.x, wid = tid >> 5, lane = tid & 31;

    {   // Whh hi/lo tiles + biases
        const uint4* src = (const uint4*)g_wt;
        uint4* dst = (uint4*)(sm + LW_OFF);
        for (int i = tid; i < 65536 / 16; i += 448) dst[i] = src[i];
        if (tid < 256) sbsum[tid] = bih[tid] + bhh[tid];
    }
    __syncthreads();

    const int G = blockIdx.x + 148 * wid;          // 16-row group id
    const bool act = (G < 2048);
    const int l7 = lane & 7;
    const uint32_t lxor = (uint32_t)l7 * 16u;
    const uint32_t aoff16 = (uint32_t)((lane >> 4) & 1) * 16u;
    const uint32_t boff16 = (uint32_t)((lane >> 3) & 1) * 16u;
    const uint32_t arow0 = (uint32_t)(wid * 16 + l7 + ((lane >> 3) & 1) * 8) * 128u;
    const uint32_t brow_l = (uint32_t)(((lane >> 4) & 1) * 8 + l7) * 128u;
    const int qr = lane >> 2, qc = lane & 3;
    const int rowL0 = wid * 16 + qr;               // local A-tile row
    const size_t rowG0 = (size_t)G * 16 + qr;      // global row

    float c[32];
#pragma unroll
    for (int i = 0; i < 32; i++) c[i] = 0.f;

#pragma unroll 1
    for (int s = 0; s < 28; s++) {
        if (s == 4) {  // swap weights: Whh -> Wih+Whh
            __syncthreads();
            const uint4* src = (const uint4*)(g_wt + 65536);
            uint4* dst = (uint4*)(sm + LW_OFF);
            for (int i = tid; i < 65536 / 16; i += 448) dst[i] = src[i];
            __syncthreads();
        }
        const uint32_t aRd = smem_base + (uint32_t)((s + 1) & 1) * LA_BUF;
        uint8_t* aWr = sm + (uint32_t)(s & 1) * LA_BUF;
        const uint32_t whi = smem_base + LW_OFF;
        const int tsel = (s < 3) ? s : 2;
        const unsigned long long* xbase = g_xg + (size_t)tsel * 128 * B_;

#pragma unroll
        for (int cd = 0; cd < 4; cd++) {
            float acc[4][2][4];
#pragma unroll
            for (int g = 0; g < 4; g++)
#pragma unroll
                for (int ds = 0; ds < 2; ds++)
#pragma unroll
                    for (int z = 0; z < 4; z++) acc[g][ds][z] = 0.f;

            if (s >= 1) {
                const uint32_t brow_cd = (uint32_t)(cd * 16) * 128u + brow_l;
#pragma unroll
                for (int kt = 0; kt < 4; kt++) {
                    const uint32_t acol = ((uint32_t)(kt * 32) + aoff16) ^ lxor;
                    const uint32_t bcol = ((uint32_t)(kt * 32) + boff16) ^ lxor;
                    uint32_t ah[4], al[4];
                    ldsm4(ah, aRd + arow0 + acol);
                    ldsm4(al, aRd + LA_LO + arow0 + acol);
                    uint32_t bh[4][4], bl[4][4];
#pragma unroll
                    for (int g = 0; g < 4; g++) {
                        ldsm4(bh[g], whi + (uint32_t)g * 8192u + brow_cd + bcol);
                        ldsm4(bl[g], whi + 32768u + (uint32_t)g * 8192u + brow_cd + bcol);
                    }
#pragma unroll
                    for (int g = 0; g < 4; g++)
#pragma unroll
                        for (int ds = 0; ds < 2; ds++) {
                            mma_bf16(acc[g][ds], ah, bh[g][ds*2], bh[g][ds*2+1]);
                            mma_bf16(acc[g][ds], al, bh[g][ds*2], bh[g][ds*2+1]);
                            mma_bf16(acc[g][ds], ah, bl[g][ds*2], bl[g][ds*2+1]);
                        }
                }
            }

            // epilogue for this 16-d chunk
            const int pbase = cd * 8 + qc;
#pragma unroll
            for (int ds = 0; ds < 2; ds++) {
                const int dbase = cd * 16 + ds * 8 + 2 * qc;
                float2 bi, bf, bg, bo;
                if (s >= 4) {
                    bi = *(const float2*)&sbsum[0 * 64 + dbase];
                    bf = *(const float2*)&sbsum[1 * 64 + dbase];
                    bg = *(const float2*)&sbsum[2 * 64 + dbase];
                    bo = *(const float2*)&sbsum[3 * 64 + dbase];
                }
#pragma unroll
                for (int rr = 0; rr < 2; rr++) {
                    const int rowL = rowL0 + rr * 8;
                    float gi0 = acc[0][ds][rr*2], gi1 = acc[0][ds][rr*2+1];
                    float gf0 = acc[1][ds][rr*2], gf1 = acc[1][ds][rr*2+1];
                    float gg0 = acc[2][ds][rr*2], gg1 = acc[2][ds][rr*2+1];
                    float go0 = acc[3][ds][rr*2], go1 = acc[3][ds][rr*2+1];
                    if (s < 4) {
                        const int pi = pbase + ds * 4;
                        float lo, hi;
                        unsigned long long v;
                        if (act) {
                            const unsigned long long* xp = xbase + (rowG0 + rr * 8);
                            v = xp[(size_t)(0 * 32 + pi) * B_]; UNPK(v, lo, hi); gi0 += lo; gi1 += hi;
                            v = xp[(size_t)(1 * 32 + pi) * B_]; UNPK(v, lo, hi); gf0 += lo; gf1 += hi;
                            v = xp[(size_t)(2 * 32 + pi) * B_]; UNPK(v, lo, hi); gg0 += lo; gg1 += hi;
                            v = xp[(size_t)(3 * 32 + pi) * B_]; UNPK(v, lo, hi); go0 += lo; go1 += hi;
                        }
                    } else {
                        gi0 += bi.x; gi1 += bi.y;
                        gf0 += bf.x; gf1 += bf.y;
                        gg0 += bg.x; gg1 += bg.y;
                        go0 += bo.x; go1 += bo.y;
                    }
                    const int ci = ((cd * 2 + ds) * 2 + rr) * 2;
                    float h0, h1;
                    lstm_cell2(gi0, gf0, gg0, go0, gi1, gf1, gg1, go1,
                               c[ci], c[ci + 1], h0, h1);
                    // split h into bf16 hi/lo and store to next-step A tile
                    uint32_t ph = pack_bf16(h0, h1);
                    float e0 = h0 - __uint_as_float(ph << 16);
                    float e1 = h1 - __uint_as_float(ph & 0xffff0000u);
                    uint32_t pl = pack_bf16(e0, e1);
                    uint32_t soff = (uint32_t)rowL * 128u +
                                    (((uint32_t)(cd * 32 + ds * 16 + qc * 4)) ^ ((uint32_t)qr * 16u));
                    *(uint32_t*)(aWr + soff) = ph;
                    *(uint32_t*)(aWr + LA_LO + soff) = pl;
                    if (s >= 3 && act) {
                        float2 o2 = make_float2(h0, h1);
                        *(float2*)(out + ((rowG0 + rr * 8) * 25 + (s - 3)) * 64 + dbase) = o2;
                    }
                }
            }
        }
        __syncwarp();
    }
}

// ---------------- host ----------------
extern "C" void kernel_launch(void* const* d_in, const int* in_sizes, int n_in,
                              void* d_out, int out_size) {
    const float* x   = (const float*)d_in[0];
    const float* W1  = (const float*)d_in[1];
    const float* b1  = (const float*)d_in[2];
    const float* g1  = (const float*)d_in[3];
    const float* be1 = (const float*)d_in[4];
    const float* W2  = (const float*)d_in[5];
    const float* b2  = (const float*)d_in[6];
    const float* g2  = (const float*)d_in[7];
    const float* be2 = (const float*)d_in[8];
    const float* W3  = (const float*)d_in[9];
    const float* b3  = (const float*)d_in[10];
    const float* Wih = (const float*)d_in[11];
    const float* Whh = (const float*)d_in[12];
    const float* bih = (const float*)d_in[13];
    const float* bhh = (const float*)d_in[14];
    float* out = (float*)d_out;

    static bool attr_done = false;
    if (!attr_done) {
        cudaFuncSetAttribute(k_mlp_fused, cudaFuncAttributeMaxDynamicSharedMemorySize, F_SMEM);
        cudaFuncSetAttribute(k_lstm_mm, cudaFuncAttributeMaxDynamicSharedMemorySize, LSTM_SMEM);
        attr_done = true;
    }

    k_mlp_fused<<<NBLK, 256, F_SMEM>>>(x, W1, b1, g1, be1, W2, b2, g2, be2,
                                       W3, b3, Wih, Whh, bih, bhh);
    k_lstm_mm<<<148, 448, LSTM_SMEM>>>(bih, bhh, out);
}

// round 13
// speedup vs baseline: 1.2405x; 1.2405x over previous
#include <cuda_runtime.h>
#include <cuda_bf16.h>
#include <cstdint>
#include <cstddef>

#define B_    32768
#define T_    3
#define D_    64
#define H_    32
#define NBLK  128   // B_/256

// ---------------- scratch (device globals: allocation-free) ----------------
__device__ unsigned long long g_xg[(size_t)T_ * 128 * B_]; // xg pairs [t][j/2][r]
__device__ float g_h1[(size_t)T_ * B_ * H_];
__device__ float g_h2[(size_t)T_ * B_ * H_];
__device__ float g_ps1[T_ * NBLK * H_];
__device__ float g_pq1[T_ * NBLK * H_];
__device__ float g_ps2[T_ * NBLK * H_];
__device__ float g_pq2[T_ * NBLK * H_];
__device__ float2 g_bn1[T_ * H_];   // (scale, shift)
__device__ float2 g_bn2[T_ * H_];
__device__ int g_c1[T_];            // last-block counters (self-resetting)
__device__ int g_c2[T_];
// weight tiles: 6 x [256 n][64 k] bf16, 128B rows, SW128-swizzled
// 0 = Whh_hi, 1 = Whh_lo, 2 = (Wih+Whh)_hi, 3 = (Wih+Whh)_lo, 4 = Wih_hi, 5 = Wih_lo
__device__ __align__(16) uint8_t g_wt[6 * 32768];

#define UNPK(v, lo, hi) do { unsigned _l, _h; \
    asm("mov.b64 {%0,%1}, %2;" : "=r"(_l), "=r"(_h) : "l"(v)); \
    lo = __uint_as_float(_l); hi = __uint_as_float(_h); } while (0)
#define PK64(lo, hi, v) asm("mov.b64 %0, {%1,%2};" : "=l"(v) : "r"(__float_as_uint(lo)), "r"(__float_as_uint(hi)))
// packed fp32x2 FMA (bit-identical to two fmaf)
#define FMA2(a, b, c) asm("fma.rn.f32x2 %0, %1, %2, %0;" : "+l"(a) : "l"(b), "l"(c))
#define BCAST2(v, x) asm("mov.b64 %0, {%1,%1};" : "=l"(v) : "r"(__float_as_uint(x)))

__device__ __forceinline__ float ex2f(float x) {
    float r; asm("ex2.approx.ftz.f32 %0, %1;" : "=f"(r) : "f"(x)); return r;
}
__device__ __forceinline__ float rcpf(float x) {
    float r; asm("rcp.approx.ftz.f32 %0, %1;" : "=f"(r) : "f"(x)); return r;
}
// paired LSTM cells: shares RCPs between the two cells. 12 MUFU / pair.
__device__ __forceinline__ void lstm_cell2(float gi0, float gf0, float gg0, float go0,
                                           float gi1, float gf1, float gg1, float go1,
                                           float& c0, float& c1, float& h0, float& h1) {
    const float L2E = 1.4426950408889634f;
    float a0 = ex2f(-L2E * gf0), u0 = ex2f(-L2E * gi0), b0 = ex2f(-2.f * L2E * gg0);
    float a1 = ex2f(-L2E * gf1), u1 = ex2f(-L2E * gi1), b1 = ex2f(-2.f * L2E * gg1);
    float pa0 = 1.f + a0, t0 = (1.f + u0) * (1.f + b0);
    float pa1 = 1.f + a1, t1 = (1.f + u1) * (1.f + b1);
    float D0 = pa0 * t0, N0 = c0 * t0 + (1.f - b0) * pa0;
    float D1 = pa1 * t1, N1 = c1 * t1 + (1.f - b1) * pa1;
    float r = rcpf(D0 * D1);
    float cn0 = N0 * (r * D1), cn1 = N1 * (r * D0);
    float v0 = ex2f(-L2E * go0), w0 = ex2f(-2.f * L2E * cn0);
    float v1 = ex2f(-L2E * go1), w1 = ex2f(-2.f * L2E * cn1);
    float P0 = (1.f + v0) * (1.f + w0), P1 = (1.f + v1) * (1.f + w1);
    float r2 = rcpf(P0 * P1);
    c0 = cn0; c1 = cn1;
    h0 = (1.f - w0) * (r2 * P1);
    h1 = (1.f - w1) * (r2 * P0);
}
__host__ __device__ __forceinline__ uint32_t swz128(uint32_t o) {
    return o ^ ((o >> 3) & 0x70);
}
__device__ __forceinline__ uint32_t pack_bf16(float lo, float hi) {
    uint32_t r;
    asm("cvt.rn.bf16x2.f32 %0, %1, %2;" : "=r"(r) : "f"(hi), "f"(lo));
    return r;
}

// ---------------- stage 1: h1 = x @ W1^T + b1, + fused BN1 stats + weight prep ----------------
__global__ void __launch_bounds__(256) k_mlp1(const float* __restrict__ x,
                                              const float* __restrict__ W1,
                                              const float* __restrict__ b1,
                                              const float* __restrict__ g1,
                                              const float* __restrict__ be1,
                                              const float* __restrict__ Wih,
                                              const float* __restrict__ Whh) {
    __shared__ __align__(16) float sW[D_ * H_];
    __shared__ float sacc[256 * 33];
    __shared__ float sr0[8 * 32], sr1[8 * 32];
    __shared__ int sflag;
    int tid = threadIdx.x;
    int t = blockIdx.y;
    int r = blockIdx.x * 256 + tid;
    for (int i = tid; i < D_ * H_; i += 256) { int j = i >> 6, k = i & 63; sW[k * H_ + j] = W1[i]; }
    __syncthreads();

    float xr[64];
    const float4* xp = (const float4*)(x + ((size_t)t * B_ + r) * D_);
#pragma unroll
    for (int i = 0; i < 16; i++) {
        float4 v = xp[i];
        xr[4*i] = v.x; xr[4*i+1] = v.y; xr[4*i+2] = v.z; xr[4*i+3] = v.w;
    }
    float acc[32];
    {
        unsigned long long acc2[16];
#pragma unroll
        for (int j = 0; j < 16; j++) acc2[j] = *(const unsigned long long*)&b1[2 * j];
#pragma unroll
        for (int k = 0; k < 64; k++) {
            unsigned long long xk2;
            BCAST2(xk2, xr[k]);
            const ulonglong2* wv = (const ulonglong2*)&sW[k * H_];
#pragma unroll
            for (int q = 0; q < 8; q++) {
                ulonglong2 w = wv[q];
                FMA2(acc2[2*q],   w.x, xk2);
                FMA2(acc2[2*q+1], w.y, xk2);
            }
        }
#pragma unroll
        for (int j = 0; j < 16; j++) UNPK(acc2[j], acc[2*j], acc[2*j+1]);
    }
    float4* op = (float4*)(g_h1 + ((size_t)t * B_ + r) * H_);
#pragma unroll
    for (int q = 0; q < 8; q++) op[q] = make_float4(acc[q*4], acc[q*4+1], acc[q*4+2], acc[q*4+3]);

    // smem transpose reduction for batch stats
#pragma unroll
    for (int j = 0; j < 32; j++) sacc[tid * 33 + j] = acc[j];
    __syncthreads();
    int part = tid >> 5, ch = tid & 31;
    {
        float s = 0.f, q = 0.f;
#pragma unroll
        for (int rr = 0; rr < 32; rr++) {
            float v = sacc[(part * 32 + rr) * 33 + ch];
            s += v; q = fmaf(v, v, q);
        }
        sr0[part * 32 + ch] = s;
        sr1[part * 32 + ch] = q;
    }
    __syncthreads();
    if (tid < 32) {
        float s = 0.f, q = 0.f;
#pragma unroll
        for (int p = 0; p < 8; p++) { s += sr0[p * 32 + tid]; q += sr1[p * 32 + tid]; }
        g_ps1[(t * NBLK + blockIdx.x) * 32 + tid] = s;
        g_pq1[(t * NBLK + blockIdx.x) * 32 + tid] = q;
    }

    // fused weight prep (bf16 hi/lo splits), frame-0 blocks 0..63 only
    if (t == 0 && blockIdx.x < 64) {
        int idx = blockIdx.x * 256 + tid;   // < 16384
        int n = idx >> 6, k = idx & 63;
        float whh = Whh[idx];
        float wih = Wih[idx];
        float ws = whh + wih;
        __nv_bfloat16 hh = __float2bfloat16_rn(whh);
        __nv_bfloat16 hl = __float2bfloat16_rn(whh - __bfloat162float(hh));
        __nv_bfloat16 sh = __float2bfloat16_rn(ws);
        __nv_bfloat16 sl = __float2bfloat16_rn(ws - __bfloat162float(sh));
        __nv_bfloat16 ih = __float2bfloat16_rn(wih);
        __nv_bfloat16 il = __float2bfloat16_rn(wih - __bfloat162float(ih));
        uint32_t off = swz128((uint32_t)(n * 128 + k * 2));
        *(__nv_bfloat16*)(g_wt + 0 * 32768 + off) = hh;
        *(__nv_bfloat16*)(g_wt + 1 * 32768 + off) = hl;
        *(__nv_bfloat16*)(g_wt + 2 * 32768 + off) = sh;
        *(__nv_bfloat16*)(g_wt + 3 * 32768 + off) = sl;
        *(__nv_bfloat16*)(g_wt + 4 * 32768 + off) = ih;
        *(__nv_bfloat16*)(g_wt + 5 * 32768 + off) = il;
    }

    // last block per frame computes BN scale/shift
    __syncthreads();
    __threadfence();
    if (tid == 0) sflag = (atomicAdd(&g_c1[t], 1) == NBLK - 1);
    __syncthreads();
    if (sflag) {
        __threadfence();
        float s = 0.f, q = 0.f;
        for (int b = part; b < NBLK; b += 8) {
            s += g_ps1[(t * NBLK + b) * 32 + ch];
            q += g_pq1[(t * NBLK + b) * 32 + ch];
        }
        sr0[part * 32 + ch] = s;
        sr1[part * 32 + ch] = q;
        __syncthreads();
        if (tid < 32) {
            float s3 = 0.f, q3 = 0.f;
#pragma unroll
            for (int p = 0; p < 8; p++) { s3 += sr0[p * 32 + tid]; q3 += sr1[p * 32 + tid]; }
            float m = s3 * (1.f / B_);
            float v = q3 * (1.f / B_) - m * m;
            float sc = g1[tid] * rsqrtf(v + 1e-5f);
            g_bn1[t * 32 + tid] = make_float2(sc, be1[tid] - m * sc);
        }
        if (tid == 0) g_c1[t] = 0;   // reset for next graph replay
    }
}

// ---------------- stage 2: h2 = relu(BN1(h1)) @ W2^T + b2, + fused BN2 stats ----------------
__global__ void __launch_bounds__(256) k_mlp2(const float* __restrict__ W2,
                                              const float* __restrict__ b2,
                                              const float* __restrict__ g2,
                                              const float* __restrict__ be2) {
    __shared__ __align__(16) float sW[H_ * H_];
    __shared__ float sacc[256 * 33];
    __shared__ float sr0[8 * 32], sr1[8 * 32];
    __shared__ int sflag;
    int tid = threadIdx.x;
    int t = blockIdx.y;
    int r = blockIdx.x * 256 + tid;
    for (int i = tid; i < H_ * H_; i += 256) { int j = i >> 5, k = i & 31; sW[k * H_ + j] = W2[i]; }
    __syncthreads();

    float a[32];
    const float4* hp = (const float4*)(g_h1 + ((size_t)t * B_ + r) * H_);
#pragma unroll
    for (int i = 0; i < 8; i++) {
        float4 v = hp[i];
        float2 s0 = g_bn1[t * 32 + i * 4 + 0]; a[i*4+0] = fmaxf(0.f, fmaf(v.x, s0.x, s0.y));
        float2 s1 = g_bn1[t * 32 + i * 4 + 1]; a[i*4+1] = fmaxf(0.f, fmaf(v.y, s1.x, s1.y));
        float2 s2 = g_bn1[t * 32 + i * 4 + 2]; a[i*4+2] = fmaxf(0.f, fmaf(v.z, s2.x, s2.y));
        float2 s3 = g_bn1[t * 32 + i * 4 + 3]; a[i*4+3] = fmaxf(0.f, fmaf(v.w, s3.x, s3.y));
    }
    float acc[32];
    {
        unsigned long long acc2[16];
#pragma unroll
        for (int j = 0; j < 16; j++) acc2[j] = *(const unsigned long long*)&b2[2 * j];
#pragma unroll
        for (int k = 0; k < 32; k++) {
            unsigned long long ak2;
            BCAST2(ak2, a[k]);
            const ulonglong2* wv = (const ulonglong2*)&sW[k * H_];
#pragma unroll
            for (int q = 0; q < 8; q++) {
                ulonglong2 w = wv[q];
                FMA2(acc2[2*q],   w.x, ak2);
                FMA2(acc2[2*q+1], w.y, ak2);
            }
        }
#pragma unroll
        for (int j = 0; j < 16; j++) UNPK(acc2[j], acc[2*j], acc[2*j+1]);
    }
    float4* op = (float4*)(g_h2 + ((size_t)t * B_ + r) * H_);
#pragma unroll
    for (int q = 0; q < 8; q++) op[q] = make_float4(acc[q*4], acc[q*4+1], acc[q*4+2], acc[q*4+3]);

#pragma unroll
    for (int j = 0; j < 32; j++) sacc[tid * 33 + j] = acc[j];
    __syncthreads();
    int part = tid >> 5, ch = tid & 31;
    {
        float s = 0.f, q = 0.f;
#pragma unroll
        for (int rr = 0; rr < 32; rr++) {
            float v = sacc[(part * 32 + rr) * 33 + ch];
            s += v; q = fmaf(v, v, q);
        }
        sr0[part * 32 + ch] = s;
        sr1[part * 32 + ch] = q;
    }
    __syncthreads();
    if (tid < 32) {
        float s = 0.f, q = 0.f;
#pragma unroll
        for (int p = 0; p < 8; p++) { s += sr0[p * 32 + tid]; q += sr1[p * 32 + tid]; }
        g_ps2[(t * NBLK + blockIdx.x) * 32 + tid] = s;
        g_pq2[(t * NBLK + blockIdx.x) * 32 + tid] = q;
    }
    __syncthreads();
    __threadfence();
    if (tid == 0) sflag = (atomicAdd(&g_c2[t], 1) == NBLK - 1);
    __syncthreads();
    if (sflag) {
        __threadfence();
        float s = 0.f, q = 0.f;
        for (int b = part; b < NBLK; b += 8) {
            s += g_ps2[(t * NBLK + b) * 32 + ch];
            q += g_pq2[(t * NBLK + b) * 32 + ch];
        }
        sr0[part * 32 + ch] = s;
        sr1[part * 32 + ch] = q;
        __syncthreads();
        if (tid < 32) {
            float s3 = 0.f, q3 = 0.f;
#pragma unroll
            for (int p = 0; p < 8; p++) { s3 += sr0[p * 32 + tid]; q3 += sr1[p * 32 + tid]; }
            float m = s3 * (1.f / B_);
            float v = q3 * (1.f / B_) - m * m;
            float sc = g2[tid] * rsqrtf(v + 1e-5f);
            g_bn2[t * 32 + tid] = make_float2(sc, be2[tid] - m * sc);
        }
        if (tid == 0) g_c2[t] = 0;
    }
}

// ---------------- HMMA helpers ----------------
__device__ __forceinline__ void mma_bf16(float d[4], const uint32_t a[4],
                                         uint32_t b0, uint32_t b1) {
    asm volatile(
        "mma.sync.aligned.m16n8k16.row.col.f32.bf16.bf16.f32 "
        "{%0,%1,%2,%3}, {%4,%5,%6,%7}, {%8,%9}, {%0,%1,%2,%3};"
        : "+f"(d[0]), "+f"(d[1]), "+f"(d[2]), "+f"(d[3])
        : "r"(a[0]), "r"(a[1]), "r"(a[2]), "r"(a[3]), "r"(b0), "r"(b1));
}
__device__ __forceinline__ void ldsm4(uint32_t r[4], uint32_t addr) {
    asm volatile("ldmatrix.sync.aligned.m8n8.x4.shared.b16 {%0,%1,%2,%3}, [%4];"
                 : "=r"(r[0]), "=r"(r[1]), "=r"(r[2]), "=r"(r[3]) : "r"(addr) : "memory");
}

// ---- stage 3: enc = relu(BN2(h2)) @ W3^T + b3; xg = enc @ Wih^T + bsum (HMMA) ----
// grid 128, loop t inside (weights loaded once)
#define M3_AHI 0u
#define M3_ALO 32768u
#define M3_WHI 65536u
#define M3_SW3 131072u
#define M3_SB  139264u
#define M3_SMEM 140288
__global__ void __launch_bounds__(256) k_mlp3(const float* __restrict__ W3,
                                              const float* __restrict__ b3,
                                              const float* __restrict__ bih,
                                              const float* __restrict__ bhh) {
    extern __shared__ __align__(16) uint8_t sm3[];
    uint32_t smem_base;
    asm("{ .reg .u64 t; cvta.to.shared.u64 t, %1; cvt.u32.u64 %0, t; }"
        : "=r"(smem_base) : "l"(sm3));
    float* sW3 = (float*)(sm3 + M3_SW3);
    float* sb  = (float*)(sm3 + M3_SB);
    const int tid = threadIdx.x, wid = tid >> 5, lane = tid & 31;

    for (int i = tid; i < 2048; i += 256) { int j = i >> 5, k = i & 31; sW3[k * 64 + j] = W3[i]; }
    {
        const uint4* src = (const uint4*)(g_wt + 4 * 32768);
        uint4* dst = (uint4*)(sm3 + M3_WHI);
        for (int i = tid; i < 65536 / 16; i += 256) dst[i] = src[i];
    }
    sb[tid] = bih[tid] + bhh[tid];
    __syncthreads();

    const int l7 = lane & 7;
    const uint32_t lxor = (uint32_t)l7 * 16u;
    const uint32_t aoff16 = (uint32_t)((lane >> 4) & 1) * 16u;
    const uint32_t boff16 = (uint32_t)((lane >> 3) & 1) * 16u;
    const uint32_t arow0 = (uint32_t)(wid * 32 + l7 + ((lane >> 3) & 1) * 8) * 128u;
    const uint32_t brow_l = (uint32_t)(((lane >> 4) & 1) * 8 + l7) * 128u;
    const int qr = lane >> 2, qc = lane & 3;
    const size_t rowG0 = (size_t)blockIdx.x * 256 + wid * 32 + qr;
    const uint32_t aHi = smem_base + M3_AHI, aLo = smem_base + M3_ALO;
    const uint32_t whi = smem_base + M3_WHI;

#pragma unroll 1
    for (int t = 0; t < T_; t++) {
        // phase 1: enc for own row (= tid)
        const size_t r = (size_t)blockIdx.x * 256 + tid;
        float a[32];
        const float4* hp = (const float4*)(g_h2 + ((size_t)t * B_ + r) * H_);
#pragma unroll
        for (int i = 0; i < 8; i++) {
            float4 v = hp[i];
            float2 s0 = g_bn2[t * 32 + i * 4 + 0]; a[i*4+0] = fmaxf(0.f, fmaf(v.x, s0.x, s0.y));
            float2 s1 = g_bn2[t * 32 + i * 4 + 1]; a[i*4+1] = fmaxf(0.f, fmaf(v.y, s1.x, s1.y));
            float2 s2 = g_bn2[t * 32 + i * 4 + 2]; a[i*4+2] = fmaxf(0.f, fmaf(v.z, s2.x, s2.y));
            float2 s3 = g_bn2[t * 32 + i * 4 + 3]; a[i*4+3] = fmaxf(0.f, fmaf(v.w, s3.x, s3.y));
        }
        float e[64];
        {
            unsigned long long e2[32];
#pragma unroll
            for (int j = 0; j < 32; j++) e2[j] = *(const unsigned long long*)&b3[2 * j];
#pragma unroll
            for (int k = 0; k < 32; k++) {
                unsigned long long ak2;
                BCAST2(ak2, a[k]);
                const ulonglong2* wv = (const ulonglong2*)&sW3[k * 64];
#pragma unroll
                for (int q = 0; q < 16; q++) {
                    ulonglong2 w = wv[q];
                    FMA2(e2[2*q],   w.x, ak2);
                    FMA2(e2[2*q+1], w.y, ak2);
                }
            }
#pragma unroll
            for (int j = 0; j < 32; j++) UNPK(e2[j], e[2*j], e[2*j+1]);
        }
        {
            const uint32_t rb = (uint32_t)tid * 128u;
            const uint32_t rx = (uint32_t)(tid & 7) * 16u;
#pragma unroll
            for (int q = 0; q < 8; q++) {
                uint32_t off = rb + (((uint32_t)q * 16u) ^ rx);
                uint32_t ph[4], pl[4];
#pragma unroll
                for (int j = 0; j < 4; j++) {
                    float e0 = e[q*8 + 2*j], e1 = e[q*8 + 2*j + 1];
                    uint32_t p = pack_bf16(e0, e1);
                    ph[j] = p;
                    pl[j] = pack_bf16(e0 - __uint_as_float(p << 16),
                                      e1 - __uint_as_float(p & 0xffff0000u));
                }
                *(uint4*)(sm3 + M3_AHI + off) = make_uint4(ph[0], ph[1], ph[2], ph[3]);
                *(uint4*)(sm3 + M3_ALO + off) = make_uint4(pl[0], pl[1], pl[2], pl[3]);
            }
        }
        __syncwarp();

        // phase 2: xg = enc @ Wih^T + bsum via HMMA (warp-private rows)
        unsigned long long* xgt = g_xg + (size_t)t * 128 * B_;
#pragma unroll
        for (int cd = 0; cd < 4; cd++) {
            float acc[2][4][2][4];
#pragma unroll
            for (int mt = 0; mt < 2; mt++)
#pragma unroll
                for (int g = 0; g < 4; g++)
#pragma unroll
                    for (int ds = 0; ds < 2; ds++)
#pragma unroll
                        for (int z = 0; z < 4; z++) acc[mt][g][ds][z] = 0.f;
            const uint32_t brow_cd = (uint32_t)(cd * 16) * 128u + brow_l;
#pragma unroll
            for (int kt = 0; kt < 4; kt++) {
                const uint32_t acol = ((uint32_t)(kt * 32) + aoff16) ^ lxor;
                const uint32_t bcol = ((uint32_t)(kt * 32) + boff16) ^ lxor;
                uint32_t ah[2][4], al[2][4];
                ldsm4(ah[0], aHi + arow0 + acol);
                ldsm4(ah[1], aHi + arow0 + 2048u + acol);
                ldsm4(al[0], aLo + arow0 + acol);
                ldsm4(al[1], aLo + arow0 + 2048u + acol);
                uint32_t bh[4][4], bl[4][4];
#pragma unroll
                for (int g = 0; g < 4; g++) {
                    ldsm4(bh[g], whi + (uint32_t)g * 8192u + brow_cd + bcol);
                    ldsm4(bl[g], whi + 32768u + (uint32_t)g * 8192u + brow_cd + bcol);
                }
#pragma unroll
                for (int mt = 0; mt < 2; mt++)
#pragma unroll
                    for (int g = 0; g < 4; g++)
#pragma unroll
                        for (int ds = 0; ds < 2; ds++) {
                            mma_bf16(acc[mt][g][ds], ah[mt], bh[g][ds*2], bh[g][ds*2+1]);
                            mma_bf16(acc[mt][g][ds], al[mt], bh[g][ds*2], bh[g][ds*2+1]);
                            mma_bf16(acc[mt][g][ds], ah[mt], bl[g][ds*2], bl[g][ds*2+1]);
                        }
            }
#pragma unroll
            for (int g = 0; g < 4; g++)
#pragma unroll
                for (int ds = 0; ds < 2; ds++) {
                    const int pi = cd * 8 + ds * 4 + qc;
                    float2 bs = *(const float2*)&sb[g * 64 + 2 * pi];
#pragma unroll
                    for (int mt = 0; mt < 2; mt++)
#pragma unroll
                        for (int rr = 0; rr < 2; rr++) {
                            float v0 = acc[mt][g][ds][rr*2]     + bs.x;
                            float v1 = acc[mt][g][ds][rr*2 + 1] + bs.y;
                            unsigned long long pk;
                            PK64(v0, v1, pk);
                            xgt[(size_t)(g * 32 + pi) * B_ + rowG0 + mt * 16 + rr * 8] = pk;
                        }
                }
        }
        __syncwarp();
    }
}

// ---------------- stage 4: HMMA 28-step LSTM, grid 148 x 448 thr (round-8 config) ----------------
#define LA_BUF   57344u
#define LA_LO    28672u
#define LW_OFF   114688u
#define LBIAS    180224u
#define LSTM_SMEM 181248

__global__ void __launch_bounds__(448, 1) k_lstm_mm(const float* __restrict__ bih,
                                                    const float* __restrict__ bhh,
                                                    float* __restrict__ out) {
    extern __shared__ __align__(16) uint8_t sm[];
    uint32_t smem_base;
    asm("{ .reg .u64 t; cvta.to.shared.u64 t, %1; cvt.u32.u64 %0, t; }"
        : "=r"(smem_base) : "l"(sm));
    float* sbsum = (float*)(sm + LBIAS);
    const int tid = threadIdx.x, wid = tid >> 5, lane = tid & 31;

    {   // Whh hi/lo tiles + biases
        const uint4* src = (const uint4*)g_wt;
        uint4* dst = (uint4*)(sm + LW_OFF);
        for (int i = tid; i < 65536 / 16; i += 448) dst[i] = src[i];
        if (tid < 256) sbsum[tid] = bih[tid] + bhh[tid];
    }
    __syncthreads();

    const int G = blockIdx.x + 148 * wid;          // 16-row group id
    const bool act = (G < 2048);
    const int l7 = lane & 7;
    const uint32_t lxor = (uint32_t)l7 * 16u;
    const uint32_t aoff16 = (uint32_t)((lane >> 4) & 1) * 16u;
    const uint32_t boff16 = (uint32_t)((lane >> 3) & 1) * 16u;
    const uint32_t arow0 = (uint32_t)(wid * 16 + l7 + ((lane >> 3) & 1) * 8) * 128u;
    const uint32_t brow_l = (uint32_t)(((lane >> 4) & 1) * 8 + l7) * 128u;
    const int qr = lane >> 2, qc = lane & 3;
    const int rowL0 = wid * 16 + qr;               // local A-tile row
    const size_t rowG0 = (size_t)G * 16 + qr;      // global row

    float c[32];
#pragma unroll
    for (int i = 0; i < 32; i++) c[i] = 0.f;

#pragma unroll 1
    for (int s = 0; s < 28; s++) {
        if (s == 4) {  // swap weights: Whh -> Wih+Whh
            __syncthreads();
            const uint4* src = (const uint4*)(g_wt + 65536);
            uint4* dst = (uint4*)(sm + LW_OFF);
            for (int i = tid; i < 65536 / 16; i += 448) dst[i] = src[i];
            __syncthreads();
        }
        const uint32_t aRd = smem_base + (uint32_t)((s + 1) & 1) * LA_BUF;
        uint8_t* aWr = sm + (uint32_t)(s & 1) * LA_BUF;
        const uint32_t whi = smem_base + LW_OFF;
        const int tsel = (s < 3) ? s : 2;
        const unsigned long long* xbase = g_xg + (size_t)tsel * 128 * B_;

#pragma unroll
        for (int cd = 0; cd < 4; cd++) {
            float acc[4][2][4];
#pragma unroll
            for (int g = 0; g < 4; g++)
#pragma unroll
                for (int ds = 0; ds < 2; ds++)
#pragma unroll
                    for (int z = 0; z < 4; z++) acc[g][ds][z] = 0.f;

            if (s >= 1) {
                const uint32_t brow_cd = (uint32_t)(cd * 16) * 128u + brow_l;
#pragma unroll
                for (int kt = 0; kt < 4; kt++) {
                    const uint32_t acol = ((uint32_t)(kt * 32) + aoff16) ^ lxor;
                    const uint32_t bcol = ((uint32_t)(kt * 32) + boff16) ^ lxor;
                    uint32_t ah[4], al[4];
                    ldsm4(ah, aRd + arow0 + acol);
                    ldsm4(al, aRd + LA_LO + arow0 + acol);
                    uint32_t bh[4][4], bl[4][4];
#pragma unroll
                    for (int g = 0; g < 4; g++) {
                        ldsm4(bh[g], whi + (uint32_t)g * 8192u + brow_cd + bcol);
                        ldsm4(bl[g], whi + 32768u + (uint32_t)g * 8192u + brow_cd + bcol);
                    }
#pragma unroll
                    for (int g = 0; g < 4; g++)
#pragma unroll
                        for (int ds = 0; ds < 2; ds++) {
                            mma_bf16(acc[g][ds], ah, bh[g][ds*2], bh[g][ds*2+1]);
                            mma_bf16(acc[g][ds], al, bh[g][ds*2], bh[g][ds*2+1]);
                            mma_bf16(acc[g][ds], ah, bl[g][ds*2], bl[g][ds*2+1]);
                        }
                }
            }

            // epilogue for this 16-d chunk
            const int pbase = cd * 8 + qc;
#pragma unroll
            for (int ds = 0; ds < 2; ds++) {
                const int dbase = cd * 16 + ds * 8 + 2 * qc;
                float2 bi, bf, bg, bo;
                if (s >= 4) {
                    bi = *(const float2*)&sbsum[0 * 64 + dbase];
                    bf = *(const float2*)&sbsum[1 * 64 + dbase];
                    bg = *(const float2*)&sbsum[2 * 64 + dbase];
                    bo = *(const float2*)&sbsum[3 * 64 + dbase];
                }
#pragma unroll
                for (int rr = 0; rr < 2; rr++) {
                    const int rowL = rowL0 + rr * 8;
                    float gi0 = acc[0][ds][rr*2], gi1 = acc[0][ds][rr*2+1];
                    float gf0 = acc[1][ds][rr*2], gf1 = acc[1][ds][rr*2+1];
                    float gg0 = acc[2][ds][rr*2], gg1 = acc[2][ds][rr*2+1];
                    float go0 = acc[3][ds][rr*2], go1 = acc[3][ds][rr*2+1];
                    if (s < 4) {
                        const int pi = pbase + ds * 4;
                        float lo, hi;
                        unsigned long long v;
                        if (act) {
                            const unsigned long long* xp = xbase + (rowG0 + rr * 8);
                            v = xp[(size_t)(0 * 32 + pi) * B_]; UNPK(v, lo, hi); gi0 += lo; gi1 += hi;
                            v = xp[(size_t)(1 * 32 + pi) * B_]; UNPK(v, lo, hi); gf0 += lo; gf1 += hi;
                            v = xp[(size_t)(2 * 32 + pi) * B_]; UNPK(v, lo, hi); gg0 += lo; gg1 += hi;
                            v = xp[(size_t)(3 * 32 + pi) * B_]; UNPK(v, lo, hi); go0 += lo; go1 += hi;
                        }
                    } else {
                        gi0 += bi.x; gi1 += bi.y;
                        gf0 += bf.x; gf1 += bf.y;
                        gg0 += bg.x; gg1 += bg.y;
                        go0 += bo.x; go1 += bo.y;
                    }
                    const int ci = ((cd * 2 + ds) * 2 + rr) * 2;
                    float h0, h1;
                    lstm_cell2(gi0, gf0, gg0, go0, gi1, gf1, gg1, go1,
                               c[ci], c[ci + 1], h0, h1);
                    // split h into bf16 hi/lo and store to next-step A tile
                    uint32_t ph = pack_bf16(h0, h1);
                    float e0 = h0 - __uint_as_float(ph << 16);
                    float e1 = h1 - __uint_as_float(ph & 0xffff0000u);
                    uint32_t pl = pack_bf16(e0, e1);
                    uint32_t soff = (uint32_t)rowL * 128u +
                                    (((uint32_t)(cd * 32 + ds * 16 + qc * 4)) ^ ((uint32_t)qr * 16u));
                    *(uint32_t*)(aWr + soff) = ph;
                    *(uint32_t*)(aWr + LA_LO + soff) = pl;
                    if (s >= 3 && act) {
                        float2 o2 = make_float2(h0, h1);
                        *(float2*)(out + ((rowG0 + rr * 8) * 25 + (s - 3)) * 64 + dbase) = o2;
                    }
                }
            }
        }
        __syncwarp();
    }
}

// ---------------- host ----------------
extern "C" void kernel_launch(void* const* d_in, const int* in_sizes, int n_in,
                              void* d_out, int out_size) {
    const float* x   = (const float*)d_in[0];
    const float* W1  = (const float*)d_in[1];
    const float* b1  = (const float*)d_in[2];
    const float* g1  = (const float*)d_in[3];
    const float* be1 = (const float*)d_in[4];
    const float* W2  = (const float*)d_in[5];
    const float* b2  = (const float*)d_in[6];
    const float* g2  = (const float*)d_in[7];
    const float* be2 = (const float*)d_in[8];
    const float* W3  = (const float*)d_in[9];
    const float* b3  = (const float*)d_in[10];
    const float* Wih = (const float*)d_in[11];
    const float* Whh = (const float*)d_in[12];
    const float* bih = (const float*)d_in[13];
    const float* bhh = (const float*)d_in[14];
    float* out = (float*)d_out;

    static bool attr_done = false;
    if (!attr_done) {
        cudaFuncSetAttribute(k_mlp3, cudaFuncAttributeMaxDynamicSharedMemorySize, M3_SMEM);
        cudaFuncSetAttribute(k_lstm_mm, cudaFuncAttributeMaxDynamicSharedMemorySize, LSTM_SMEM);
        attr_done = true;
    }

    dim3 gmlp(NBLK, T_);
    k_mlp1<<<gmlp, 256>>>(x, W1, b1, g1, be1, Wih, Whh);
    k_mlp2<<<gmlp, 256>>>(W2, b2, g2, be2);
    k_mlp3<<<NBLK, 256, M3_SMEM>>>(W3, b3, bih, bhh);
    k_lstm_mm<<<148, 448, LSTM_SMEM>>>(bih, bhh, out);
}

// round 14
// speedup vs baseline: 1.4818x; 1.1946x over previous
#include <cuda_runtime.h>
#include <cuda_bf16.h>
#include <cuda_fp16.h>
#include <cstdint>
#include <cstddef>

#define B_    32768
#define T_    3
#define D_    64
#define H_    32
#define NBLK  128   // B_/256

// ---------------- scratch (device globals: allocation-free) ----------------
__device__ unsigned long long g_xg[(size_t)T_ * 128 * B_]; // xg pairs [t][j/2][r]
__device__ float g_h1[(size_t)T_ * B_ * H_];
__device__ float g_h2[(size_t)T_ * B_ * H_];
__device__ float g_ps1[T_ * NBLK * H_];
__device__ float g_pq1[T_ * NBLK * H_];
__device__ float g_ps2[T_ * NBLK * H_];
__device__ float g_pq2[T_ * NBLK * H_];
__device__ float2 g_bn1[T_ * H_];   // (scale, shift)
__device__ float2 g_bn2[T_ * H_];
__device__ int g_c1[T_];            // last-block counters (self-resetting)
__device__ int g_c2[T_];
// weight tiles: 4 x [256 n][64 k], 128B rows, SW128-swizzled
// 0 = Whh fp16, 1 = (Wih+Whh) fp16, 2 = Wih_hi bf16, 3 = Wih_lo bf16
__device__ __align__(16) uint8_t g_wt[4 * 32768];

#define UNPK(v, lo, hi) do { unsigned _l, _h; \
    asm("mov.b64 {%0,%1}, %2;" : "=r"(_l), "=r"(_h) : "l"(v)); \
    lo = __uint_as_float(_l); hi = __uint_as_float(_h); } while (0)
#define PK64(lo, hi, v) asm("mov.b64 %0, {%1,%2};" : "=l"(v) : "r"(__float_as_uint(lo)), "r"(__float_as_uint(hi)))
// packed fp32x2 FMA (bit-identical to two fmaf)
#define FMA2(a, b, c) asm("fma.rn.f32x2 %0, %1, %2, %0;" : "+l"(a) : "l"(b), "l"(c))
#define BCAST2(v, x) asm("mov.b64 %0, {%1,%1};" : "=l"(v) : "r"(__float_as_uint(x)))

__device__ __forceinline__ float ex2f(float x) {
    float r; asm("ex2.approx.ftz.f32 %0, %1;" : "=f"(r) : "f"(x)); return r;
}
__device__ __forceinline__ float rcpf(float x) {
    float r; asm("rcp.approx.ftz.f32 %0, %1;" : "=f"(r) : "f"(x)); return r;
}
// paired LSTM cells: shares RCPs between the two cells. 12 MUFU / pair.
__device__ __forceinline__ void lstm_cell2(float gi0, float gf0, float gg0, float go0,
                                           float gi1, float gf1, float gg1, float go1,
                                           float& c0, float& c1, float& h0, float& h1) {
    const float L2E = 1.4426950408889634f;
    float a0 = ex2f(-L2E * gf0), u0 = ex2f(-L2E * gi0), b0 = ex2f(-2.f * L2E * gg0);
    float a1 = ex2f(-L2E * gf1), u1 = ex2f(-L2E * gi1), b1 = ex2f(-2.f * L2E * gg1);
    float pa0 = 1.f + a0, t0 = (1.f + u0) * (1.f + b0);
    float pa1 = 1.f + a1, t1 = (1.f + u1) * (1.f + b1);
    float D0 = pa0 * t0, N0 = c0 * t0 + (1.f - b0) * pa0;
    float D1 = pa1 * t1, N1 = c1 * t1 + (1.f - b1) * pa1;
    float r = rcpf(D0 * D1);
    float cn0 = N0 * (r * D1), cn1 = N1 * (r * D0);
    float v0 = ex2f(-L2E * go0), w0 = ex2f(-2.f * L2E * cn0);
    float v1 = ex2f(-L2E * go1), w1 = ex2f(-2.f * L2E * cn1);
    float P0 = (1.f + v0) * (1.f + w0), P1 = (1.f + v1) * (1.f + w1);
    float r2 = rcpf(P0 * P1);
    c0 = cn0; c1 = cn1;
    h0 = (1.f - w0) * (r2 * P1);
    h1 = (1.f - w1) * (r2 * P0);
}
__host__ __device__ __forceinline__ uint32_t swz128(uint32_t o) {
    return o ^ ((o >> 3) & 0x70);
}
__device__ __forceinline__ uint32_t pack_bf16(float lo, float hi) {
    uint32_t r;
    asm("cvt.rn.bf16x2.f32 %0, %1, %2;" : "=r"(r) : "f"(hi), "f"(lo));
    return r;
}

// ---------------- stage 1: h1 = x @ W1^T + b1, + fused BN1 stats + weight prep ----------------
__global__ void __launch_bounds__(256) k_mlp1(const float* __restrict__ x,
                                              const float* __restrict__ W1,
                                              const float* __restrict__ b1,
                                              const float* __restrict__ g1,
                                              const float* __restrict__ be1,
                                              const float* __restrict__ Wih,
                                              const float* __restrict__ Whh) {
    __shared__ __align__(16) float sW[D_ * H_];
    __shared__ float sacc[256 * 33];
    __shared__ float sr0[8 * 32], sr1[8 * 32];
    __shared__ int sflag;
    int tid = threadIdx.x;
    int t = blockIdx.y;
    int r = blockIdx.x * 256 + tid;
    for (int i = tid; i < D_ * H_; i += 256) { int j = i >> 6, k = i & 63; sW[k * H_ + j] = W1[i]; }
    __syncthreads();

    float xr[64];
    const float4* xp = (const float4*)(x + ((size_t)t * B_ + r) * D_);
#pragma unroll
    for (int i = 0; i < 16; i++) {
        float4 v = xp[i];
        xr[4*i] = v.x; xr[4*i+1] = v.y; xr[4*i+2] = v.z; xr[4*i+3] = v.w;
    }
    float acc[32];
    {
        unsigned long long acc2[16];
#pragma unroll
        for (int j = 0; j < 16; j++) acc2[j] = *(const unsigned long long*)&b1[2 * j];
#pragma unroll
        for (int k = 0; k < 64; k++) {
            unsigned long long xk2;
            BCAST2(xk2, xr[k]);
            const ulonglong2* wv = (const ulonglong2*)&sW[k * H_];
#pragma unroll
            for (int q = 0; q < 8; q++) {
                ulonglong2 w = wv[q];
                FMA2(acc2[2*q],   w.x, xk2);
                FMA2(acc2[2*q+1], w.y, xk2);
            }
        }
#pragma unroll
        for (int j = 0; j < 16; j++) UNPK(acc2[j], acc[2*j], acc[2*j+1]);
    }
    float4* op = (float4*)(g_h1 + ((size_t)t * B_ + r) * H_);
#pragma unroll
    for (int q = 0; q < 8; q++) op[q] = make_float4(acc[q*4], acc[q*4+1], acc[q*4+2], acc[q*4+3]);

    // smem transpose reduction for batch stats
#pragma unroll
    for (int j = 0; j < 32; j++) sacc[tid * 33 + j] = acc[j];
    __syncthreads();
    int part = tid >> 5, ch = tid & 31;
    {
        float s = 0.f, q = 0.f;
#pragma unroll
        for (int rr = 0; rr < 32; rr++) {
            float v = sacc[(part * 32 + rr) * 33 + ch];
            s += v; q = fmaf(v, v, q);
        }
        sr0[part * 32 + ch] = s;
        sr1[part * 32 + ch] = q;
    }
    __syncthreads();
    if (tid < 32) {
        float s = 0.f, q = 0.f;
#pragma unroll
        for (int p = 0; p < 8; p++) { s += sr0[p * 32 + tid]; q += sr1[p * 32 + tid]; }
        g_ps1[(t * NBLK + blockIdx.x) * 32 + tid] = s;
        g_pq1[(t * NBLK + blockIdx.x) * 32 + tid] = q;
    }

    // fused weight prep, frame-0 blocks 0..63 only
    if (t == 0 && blockIdx.x < 64) {
        int idx = blockIdx.x * 256 + tid;   // < 16384
        int n = idx >> 6, k = idx & 63;
        float whh = Whh[idx];
        float wih = Wih[idx];
        float ws = whh + wih;
        __half hf = __float2half_rn(whh);
        __half sf = __float2half_rn(ws);
        __nv_bfloat16 ih = __float2bfloat16_rn(wih);
        __nv_bfloat16 il = __float2bfloat16_rn(wih - __bfloat162float(ih));
        uint32_t off = swz128((uint32_t)(n * 128 + k * 2));
        *(__half*)(g_wt + 0 * 32768 + off) = hf;
        *(__half*)(g_wt + 1 * 32768 + off) = sf;
        *(__nv_bfloat16*)(g_wt + 2 * 32768 + off) = ih;
        *(__nv_bfloat16*)(g_wt + 3 * 32768 + off) = il;
    }

    // last block per frame computes BN scale/shift
    __syncthreads();
    __threadfence();
    if (tid == 0) sflag = (atomicAdd(&g_c1[t], 1) == NBLK - 1);
    __syncthreads();
    if (sflag) {
        __threadfence();
        float s = 0.f, q = 0.f;
        for (int b = part; b < NBLK; b += 8) {
            s += g_ps1[(t * NBLK + b) * 32 + ch];
            q += g_pq1[(t * NBLK + b) * 32 + ch];
        }
        sr0[part * 32 + ch] = s;
        sr1[part * 32 + ch] = q;
        __syncthreads();
        if (tid < 32) {
            float s3 = 0.f, q3 = 0.f;
#pragma unroll
            for (int p = 0; p < 8; p++) { s3 += sr0[p * 32 + tid]; q3 += sr1[p * 32 + tid]; }
            float m = s3 * (1.f / B_);
            float v = q3 * (1.f / B_) - m * m;
            float sc = g1[tid] * rsqrtf(v + 1e-5f);
            g_bn1[t * 32 + tid] = make_float2(sc, be1[tid] - m * sc);
        }
        if (tid == 0) g_c1[t] = 0;   // reset for next graph replay
    }
}

// ---------------- stage 2: h2 = relu(BN1(h1)) @ W2^T + b2, + fused BN2 stats ----------------
__global__ void __launch_bounds__(256) k_mlp2(const float* __restrict__ W2,
                                              const float* __restrict__ b2,
                                              const float* __restrict__ g2,
                                              const float* __restrict__ be2) {
    __shared__ __align__(16) float sW[H_ * H_];
    __shared__ float sacc[256 * 33];
    __shared__ float sr0[8 * 32], sr1[8 * 32];
    __shared__ int sflag;
    int tid = threadIdx.x;
    int t = blockIdx.y;
    int r = blockIdx.x * 256 + tid;
    for (int i = tid; i < H_ * H_; i += 256) { int j = i >> 5, k = i & 31; sW[k * H_ + j] = W2[i]; }
    __syncthreads();

    float a[32];
    const float4* hp = (const float4*)(g_h1 + ((size_t)t * B_ + r) * H_);
#pragma unroll
    for (int i = 0; i < 8; i++) {
        float4 v = hp[i];
        float2 s0 = g_bn1[t * 32 + i * 4 + 0]; a[i*4+0] = fmaxf(0.f, fmaf(v.x, s0.x, s0.y));
        float2 s1 = g_bn1[t * 32 + i * 4 + 1]; a[i*4+1] = fmaxf(0.f, fmaf(v.y, s1.x, s1.y));
        float2 s2 = g_bn1[t * 32 + i * 4 + 2]; a[i*4+2] = fmaxf(0.f, fmaf(v.z, s2.x, s2.y));
        float2 s3 = g_bn1[t * 32 + i * 4 + 3]; a[i*4+3] = fmaxf(0.f, fmaf(v.w, s3.x, s3.y));
    }
    float acc[32];
    {
        unsigned long long acc2[16];
#pragma unroll
        for (int j = 0; j < 16; j++) acc2[j] = *(const unsigned long long*)&b2[2 * j];
#pragma unroll
        for (int k = 0; k < 32; k++) {
            unsigned long long ak2;
            BCAST2(ak2, a[k]);
            const ulonglong2* wv = (const ulonglong2*)&sW[k * H_];
#pragma unroll
            for (int q = 0; q < 8; q++) {
                ulonglong2 w = wv[q];
                FMA2(acc2[2*q],   w.x, ak2);
                FMA2(acc2[2*q+1], w.y, ak2);
            }
        }
#pragma unroll
        for (int j = 0; j < 16; j++) UNPK(acc2[j], acc[2*j], acc[2*j+1]);
    }
    float4* op = (float4*)(g_h2 + ((size_t)t * B_ + r) * H_);
#pragma unroll
    for (int q = 0; q < 8; q++) op[q] = make_float4(acc[q*4], acc[q*4+1], acc[q*4+2], acc[q*4+3]);

#pragma unroll
    for (int j = 0; j < 32; j++) sacc[tid * 33 + j] = acc[j];
    __syncthreads();
    int part = tid >> 5, ch = tid & 31;
    {
        float s = 0.f, q = 0.f;
#pragma unroll
        for (int rr = 0; rr < 32; rr++) {
            float v = sacc[(part * 32 + rr) * 33 + ch];
            s += v; q = fmaf(v, v, q);
        }
        sr0[part * 32 + ch] = s;
        sr1[part * 32 + ch] = q;
    }
    __syncthreads();
    if (tid < 32) {
        float s = 0.f, q = 0.f;
#pragma unroll
        for (int p = 0; p < 8; p++) { s += sr0[p * 32 + tid]; q += sr1[p * 32 + tid]; }
        g_ps2[(t * NBLK + blockIdx.x) * 32 + tid] = s;
        g_pq2[(t * NBLK + blockIdx.x) * 32 + tid] = q;
    }
    __syncthreads();
    __threadfence();
    if (tid == 0) sflag = (atomicAdd(&g_c2[t], 1) == NBLK - 1);
    __syncthreads();
    if (sflag) {
        __threadfence();
        float s = 0.f, q = 0.f;
        for (int b = part; b < NBLK; b += 8) {
            s += g_ps2[(t * NBLK + b) * 32 + ch];
            q += g_pq2[(t * NBLK + b) * 32 + ch];
        }
        sr0[part * 32 + ch] = s;
        sr1[part * 32 + ch] = q;
        __syncthreads();
        if (tid < 32) {
            float s3 = 0.f, q3 = 0.f;
#pragma unroll
            for (int p = 0; p < 8; p++) { s3 += sr0[p * 32 + tid]; q3 += sr1[p * 32 + tid]; }
            float m = s3 * (1.f / B_);
            float v = q3 * (1.f / B_) - m * m;
            float sc = g2[tid] * rsqrtf(v + 1e-5f);
            g_bn2[t * 32 + tid] = make_float2(sc, be2[tid] - m * sc);
        }
        if (tid == 0) g_c2[t] = 0;
    }
}

// ---------------- HMMA helpers ----------------
__device__ __forceinline__ void mma_bf16(float d[4], const uint32_t a[4],
                                         uint32_t b0, uint32_t b1) {
    asm volatile(
        "mma.sync.aligned.m16n8k16.row.col.f32.bf16.bf16.f32 "
        "{%0,%1,%2,%3}, {%4,%5,%6,%7}, {%8,%9}, {%0,%1,%2,%3};"
        : "+f"(d[0]), "+f"(d[1]), "+f"(d[2]), "+f"(d[3])
        : "r"(a[0]), "r"(a[1]), "r"(a[2]), "r"(a[3]), "r"(b0), "r"(b1));
}
__device__ __forceinline__ void mma_f16(float d[4], const uint32_t a[4],
                                        uint32_t b0, uint32_t b1) {
    asm volatile(
        "mma.sync.aligned.m16n8k16.row.col.f32.f16.f16.f32 "
        "{%0,%1,%2,%3}, {%4,%5,%6,%7}, {%8,%9}, {%0,%1,%2,%3};"
        : "+f"(d[0]), "+f"(d[1]), "+f"(d[2]), "+f"(d[3])
        : "r"(a[0]), "r"(a[1]), "r"(a[2]), "r"(a[3]), "r"(b0), "r"(b1));
}
__device__ __forceinline__ void ldsm4(uint32_t r[4], uint32_t addr) {
    asm volatile("ldmatrix.sync.aligned.m8n8.x4.shared.b16 {%0,%1,%2,%3}, [%4];"
                 : "=r"(r[0]), "=r"(r[1]), "=r"(r[2]), "=r"(r[3]) : "r"(addr) : "memory");
}

// ---- stage 3: enc = relu(BN2(h2)) @ W3^T + b3; xg = enc @ Wih^T + bsum (bf16 3-term HMMA) ----
#define M3_AHI 0u
#define M3_ALO 32768u
#define M3_WHI 65536u
#define M3_SW3 131072u
#define M3_SB  139264u
#define M3_SMEM 140288
__global__ void __launch_bounds__(256) k_mlp3(const float* __restrict__ W3,
                                              const float* __restrict__ b3,
                                              const float* __restrict__ bih,
                                              const float* __restrict__ bhh) {
    extern __shared__ __align__(16) uint8_t sm3[];
    uint32_t smem_base;
    asm("{ .reg .u64 t; cvta.to.shared.u64 t, %1; cvt.u32.u64 %0, t; }"
        : "=r"(smem_base) : "l"(sm3));
    float* sW3 = (float*)(sm3 + M3_SW3);
    float* sb  = (float*)(sm3 + M3_SB);
    const int tid = threadIdx.x, wid = tid >> 5, lane = tid & 31;

    for (int i = tid; i < 2048; i += 256) { int j = i >> 5, k = i & 31; sW3[k * 64 + j] = W3[i]; }
    {
        const uint4* src = (const uint4*)(g_wt + 2 * 32768);   // Wih hi/lo bf16 (64KB)
        uint4* dst = (uint4*)(sm3 + M3_WHI);
        for (int i = tid; i < 65536 / 16; i += 256) dst[i] = src[i];
    }
    sb[tid] = bih[tid] + bhh[tid];
    __syncthreads();

    const int l7 = lane & 7;
    const uint32_t lxor = (uint32_t)l7 * 16u;
    const uint32_t aoff16 = (uint32_t)((lane >> 4) & 1) * 16u;
    const uint32_t boff16 = (uint32_t)((lane >> 3) & 1) * 16u;
    const uint32_t arow0 = (uint32_t)(wid * 32 + l7 + ((lane >> 3) & 1) * 8) * 128u;
    const uint32_t brow_l = (uint32_t)(((lane >> 4) & 1) * 8 + l7) * 128u;
    const int qr = lane >> 2, qc = lane & 3;
    const size_t rowG0 = (size_t)blockIdx.x * 256 + wid * 32 + qr;
    const uint32_t aHi = smem_base + M3_AHI, aLo = smem_base + M3_ALO;
    const uint32_t whi = smem_base + M3_WHI;

#pragma unroll 1
    for (int t = 0; t < T_; t++) {
        // phase 1: enc for own row (= tid)
        const size_t r = (size_t)blockIdx.x * 256 + tid;
        float a[32];
        const float4* hp = (const float4*)(g_h2 + ((size_t)t * B_ + r) * H_);
#pragma unroll
        for (int i = 0; i < 8; i++) {
            float4 v = hp[i];
            float2 s0 = g_bn2[t * 32 + i * 4 + 0]; a[i*4+0] = fmaxf(0.f, fmaf(v.x, s0.x, s0.y));
            float2 s1 = g_bn2[t * 32 + i * 4 + 1]; a[i*4+1] = fmaxf(0.f, fmaf(v.y, s1.x, s1.y));
            float2 s2 = g_bn2[t * 32 + i * 4 + 2]; a[i*4+2] = fmaxf(0.f, fmaf(v.z, s2.x, s2.y));
            float2 s3 = g_bn2[t * 32 + i * 4 + 3]; a[i*4+3] = fmaxf(0.f, fmaf(v.w, s3.x, s3.y));
        }
        float e[64];
        {
            unsigned long long e2[32];
#pragma unroll
            for (int j = 0; j < 32; j++) e2[j] = *(const unsigned long long*)&b3[2 * j];
#pragma unroll
            for (int k = 0; k < 32; k++) {
                unsigned long long ak2;
                BCAST2(ak2, a[k]);
                const ulonglong2* wv = (const ulonglong2*)&sW3[k * 64];
#pragma unroll
                for (int q = 0; q < 16; q++) {
                    ulonglong2 w = wv[q];
                    FMA2(e2[2*q],   w.x, ak2);
                    FMA2(e2[2*q+1], w.y, ak2);
                }
            }
#pragma unroll
            for (int j = 0; j < 32; j++) UNPK(e2[j], e[2*j], e[2*j+1]);
        }
        {
            const uint32_t rb = (uint32_t)tid * 128u;
            const uint32_t rx = (uint32_t)(tid & 7) * 16u;
#pragma unroll
            for (int q = 0; q < 8; q++) {
                uint32_t off = rb + (((uint32_t)q * 16u) ^ rx);
                uint32_t ph[4], pl[4];
#pragma unroll
                for (int j = 0; j < 4; j++) {
                    float e0 = e[q*8 + 2*j], e1 = e[q*8 + 2*j + 1];
                    uint32_t p = pack_bf16(e0, e1);
                    ph[j] = p;
                    pl[j] = pack_bf16(e0 - __uint_as_float(p << 16),
                                      e1 - __uint_as_float(p & 0xffff0000u));
                }
                *(uint4*)(sm3 + M3_AHI + off) = make_uint4(ph[0], ph[1], ph[2], ph[3]);
                *(uint4*)(sm3 + M3_ALO + off) = make_uint4(pl[0], pl[1], pl[2], pl[3]);
            }
        }
        __syncwarp();

        // phase 2: xg = enc @ Wih^T + bsum via HMMA (warp-private rows)
        unsigned long long* xgt = g_xg + (size_t)t * 128 * B_;
#pragma unroll
        for (int cd = 0; cd < 4; cd++) {
            float acc[2][4][2][4];
#pragma unroll
            for (int mt = 0; mt < 2; mt++)
#pragma unroll
                for (int g = 0; g < 4; g++)
#pragma unroll
                    for (int ds = 0; ds < 2; ds++)
#pragma unroll
                        for (int z = 0; z < 4; z++) acc[mt][g][ds][z] = 0.f;
            const uint32_t brow_cd = (uint32_t)(cd * 16) * 128u + brow_l;
#pragma unroll
            for (int kt = 0; kt < 4; kt++) {
                const uint32_t acol = ((uint32_t)(kt * 32) + aoff16) ^ lxor;
                const uint32_t bcol = ((uint32_t)(kt * 32) + boff16) ^ lxor;
                uint32_t ah[2][4], al[2][4];
                ldsm4(ah[0], aHi + arow0 + acol);
                ldsm4(ah[1], aHi + arow0 + 2048u + acol);
                ldsm4(al[0], aLo + arow0 + acol);
                ldsm4(al[1], aLo + arow0 + 2048u + acol);
                uint32_t bh[4][4], bl[4][4];
#pragma unroll
                for (int g = 0; g < 4; g++) {
                    ldsm4(bh[g], whi + (uint32_t)g * 8192u + brow_cd + bcol);
                    ldsm4(bl[g], whi + 32768u + (uint32_t)g * 8192u + brow_cd + bcol);
                }
#pragma unroll
                for (int mt = 0; mt < 2; mt++)
#pragma unroll
                    for (int g = 0; g < 4; g++)
#pragma unroll
                        for (int ds = 0; ds < 2; ds++) {
                            mma_bf16(acc[mt][g][ds], ah[mt], bh[g][ds*2], bh[g][ds*2+1]);
                            mma_bf16(acc[mt][g][ds], al[mt], bh[g][ds*2], bh[g][ds*2+1]);
                            mma_bf16(acc[mt][g][ds], ah[mt], bl[g][ds*2], bl[g][ds*2+1]);
                        }
            }
#pragma unroll
            for (int g = 0; g < 4; g++)
#pragma unroll
                for (int ds = 0; ds < 2; ds++) {
                    const int pi = cd * 8 + ds * 4 + qc;
                    float2 bs = *(const float2*)&sb[g * 64 + 2 * pi];
#pragma unroll
                    for (int mt = 0; mt < 2; mt++)
#pragma unroll
                        for (int rr = 0; rr < 2; rr++) {
                            float v0 = acc[mt][g][ds][rr*2]     + bs.x;
                            float v1 = acc[mt][g][ds][rr*2 + 1] + bs.y;
                            unsigned long long pk;
                            PK64(v0, v1, pk);
                            xgt[(size_t)(g * 32 + pi) * B_ + rowG0 + mt * 16 + rr * 8] = pk;
                        }
                }
        }
        __syncwarp();
    }
}

// ---------------- stage 4: fp16 2-term HMMA 28-step LSTM, grid 148 x 448 ----------------
// smem: A dbl buffers 2x57344 (hi@0, lo@28672 within each), W fp16 32KB @114688, bias @147456
#define LA_BUF   57344u
#define LA_LO    28672u
#define LW_OFF   114688u
#define LBIAS    147456u
#define LSTM_SMEM 148480

__global__ void __launch_bounds__(448, 1) k_lstm_mm(const float* __restrict__ bih,
                                                    const float* __restrict__ bhh,
                                                    float* __restrict__ out) {
    extern __shared__ __align__(16) uint8_t sm[];
    uint32_t smem_base;
    asm("{ .reg .u64 t; cvta.to.shared.u64 t, %1; cvt.u32.u64 %0, t; }"
        : "=r"(smem_base) : "l"(sm));
    float* sbsum = (float*)(sm + LBIAS);
    const int tid = threadIdx.x, wid = tid >> 5, lane = tid & 31;

    {   // Whh fp16 tile + biases
        const uint4* src = (const uint4*)g_wt;
        uint4* dst = (uint4*)(sm + LW_OFF);
        for (int i = tid; i < 32768 / 16; i += 448) dst[i] = src[i];
        if (tid < 256) sbsum[tid] = bih[tid] + bhh[tid];
    }
    __syncthreads();

    const int G = blockIdx.x + 148 * wid;          // 16-row group id
    const bool act = (G < 2048);
    const int l7 = lane & 7;
    const uint32_t lxor = (uint32_t)l7 * 16u;
    const uint32_t aoff16 = (uint32_t)((lane >> 4) & 1) * 16u;
    const uint32_t boff16 = (uint32_t)((lane >> 3) & 1) * 16u;
    const uint32_t arow0 = (uint32_t)(wid * 16 + l7 + ((lane >> 3) & 1) * 8) * 128u;
    const uint32_t brow_l = (uint32_t)(((lane >> 4) & 1) * 8 + l7) * 128u;
    const int qr = lane >> 2, qc = lane & 3;
    const int rowL0 = wid * 16 + qr;               // local A-tile row
    const size_t rowG0 = (size_t)G * 16 + qr;      // global row

    float c[32];
#pragma unroll
    for (int i = 0; i < 32; i++) c[i] = 0.f;

#pragma unroll 1
    for (int s = 0; s < 28; s++) {
        if (s == 4) {  // swap weights: Whh -> Wih+Whh (fp16)
            __syncthreads();
            const uint4* src = (const uint4*)(g_wt + 32768);
            uint4* dst = (uint4*)(sm + LW_OFF);
            for (int i = tid; i < 32768 / 16; i += 448) dst[i] = src[i];
            __syncthreads();
        }
        const uint32_t aRd = smem_base + (uint32_t)((s + 1) & 1) * LA_BUF;
        uint8_t* aWr = sm + (uint32_t)(s & 1) * LA_BUF;
        const uint32_t wBase = smem_base + LW_OFF;
        const int tsel = (s < 3) ? s : 2;
        const unsigned long long* xbase = g_xg + (size_t)tsel * 128 * B_;

#pragma unroll
        for (int cd = 0; cd < 4; cd++) {
            float acc[4][2][4];
#pragma unroll
            for (int g = 0; g < 4; g++)
#pragma unroll
                for (int ds = 0; ds < 2; ds++)
#pragma unroll
                    for (int z = 0; z < 4; z++) acc[g][ds][z] = 0.f;

            if (s >= 1) {
                const uint32_t brow_cd = (uint32_t)(cd * 16) * 128u + brow_l;
#pragma unroll
                for (int kt = 0; kt < 4; kt++) {
                    const uint32_t acol = ((uint32_t)(kt * 32) + aoff16) ^ lxor;
                    const uint32_t bcol = ((uint32_t)(kt * 32) + boff16) ^ lxor;
                    uint32_t ah[4], al[4];
                    ldsm4(ah, aRd + arow0 + acol);
                    ldsm4(al, aRd + LA_LO + arow0 + acol);
                    uint32_t wf[4][4];
#pragma unroll
                    for (int g = 0; g < 4; g++)
                        ldsm4(wf[g], wBase + (uint32_t)g * 8192u + brow_cd + bcol);
#pragma unroll
                    for (int g = 0; g < 4; g++)
#pragma unroll
                        for (int ds = 0; ds < 2; ds++) {
                            mma_f16(acc[g][ds], ah, wf[g][ds*2], wf[g][ds*2+1]);
                            mma_f16(acc[g][ds], al, wf[g][ds*2], wf[g][ds*2+1]);
                        }
                }
            }

            // epilogue for this 16-d chunk
            const int pbase = cd * 8 + qc;
#pragma unroll
            for (int ds = 0; ds < 2; ds++) {
                const int dbase = cd * 16 + ds * 8 + 2 * qc;
                float2 bi, bf, bg, bo;
                if (s >= 4) {
                    bi = *(const float2*)&sbsum[0 * 64 + dbase];
                    bf = *(const float2*)&sbsum[1 * 64 + dbase];
                    bg = *(const float2*)&sbsum[2 * 64 + dbase];
                    bo = *(const float2*)&sbsum[3 * 64 + dbase];
                }
#pragma unroll
                for (int rr = 0; rr < 2; rr++) {
                    const int rowL = rowL0 + rr * 8;
                    float gi0 = acc[0][ds][rr*2], gi1 = acc[0][ds][rr*2+1];
                    float gf0 = acc[1][ds][rr*2], gf1 = acc[1][ds][rr*2+1];
                    float gg0 = acc[2][ds][rr*2], gg1 = acc[2][ds][rr*2+1];
                    float go0 = acc[3][ds][rr*2], go1 = acc[3][ds][rr*2+1];
                    if (s < 4) {
                        const int pi = pbase + ds * 4;
                        float lo, hi;
                        unsigned long long v;
                        if (act) {
                            const unsigned long long* xp = xbase + (rowG0 + rr * 8);
                            v = xp[(size_t)(0 * 32 + pi) * B_]; UNPK(v, lo, hi); gi0 += lo; gi1 += hi;
                            v = xp[(size_t)(1 * 32 + pi) * B_]; UNPK(v, lo, hi); gf0 += lo; gf1 += hi;
                            v = xp[(size_t)(2 * 32 + pi) * B_]; UNPK(v, lo, hi); gg0 += lo; gg1 += hi;
                            v = xp[(size_t)(3 * 32 + pi) * B_]; UNPK(v, lo, hi); go0 += lo; go1 += hi;
                        }
                    } else {
                        gi0 += bi.x; gi1 += bi.y;
                        gf0 += bf.x; gf1 += bf.y;
                        gg0 += bg.x; gg1 += bg.y;
                        go0 += bo.x; go1 += bo.y;
                    }
                    const int ci = ((cd * 2 + ds) * 2 + rr) * 2;
                    float h0, h1;
                    lstm_cell2(gi0, gf0, gg0, go0, gi1, gf1, gg1, go1,
                               c[ci], c[ci + 1], h0, h1);
                    // split h into fp16 hi/lo and store to next-step A tile
                    __half2 hp2 = __floats2half2_rn(h0, h1);
                    uint32_t ph;
                    asm("mov.b32 %0, {%1,%2};" : "=r"(ph)
                        : "h"(__half_as_ushort(__low2half(hp2))),
                          "h"(__half_as_ushort(__high2half(hp2))));
                    float e0 = h0 - __half2float(__low2half(hp2));
                    float e1 = h1 - __half2float(__high2half(hp2));
                    __half2 lp2 = __floats2half2_rn(e0, e1);
                    uint32_t pl;
                    asm("mov.b32 %0, {%1,%2};" : "=r"(pl)
                        : "h"(__half_as_ushort(__low2half(lp2))),
                          "h"(__half_as_ushort(__high2half(lp2))));
                    uint32_t soff = (uint32_t)rowL * 128u +
                                    (((uint32_t)(cd * 32 + ds * 16 + qc * 4)) ^ ((uint32_t)qr * 16u));
                    *(uint32_t*)(aWr + soff) = ph;
                    *(uint32_t*)(aWr + LA_LO + soff) = pl;
                    if (s >= 3 && act) {
                        float2 o2 = make_float2(h0, h1);
                        *(float2*)(out + ((rowG0 + rr * 8) * 25 + (s - 3)) * 64 + dbase) = o2;
                    }
                }
            }
        }
        __syncwarp();
    }
}

// ---------------- host ----------------
extern "C" void kernel_launch(void* const* d_in, const int* in_sizes, int n_in,
                              void* d_out, int out_size) {
    const float* x   = (const float*)d_in[0];
    const float* W1  = (const float*)d_in[1];
    const float* b1  = (const float*)d_in[2];
    const float* g1  = (const float*)d_in[3];
    const float* be1 = (const float*)d_in[4];
    const float* W2  = (const float*)d_in[5];
    const float* b2  = (const float*)d_in[6];
    const float* g2  = (const float*)d_in[7];
    const float* be2 = (const float*)d_in[8];
    const float* W3  = (const float*)d_in[9];
    const float* b3  = (const float*)d_in[10];
    const float* Wih = (const float*)d_in[11];
    const float* Whh = (const float*)d_in[12];
    const float* bih = (const float*)d_in[13];
    const float* bhh = (const float*)d_in[14];
    float* out = (float*)d_out;

    static bool attr_done = false;
    if (!attr_done) {
        cudaFuncSetAttribute(k_mlp3, cudaFuncAttributeMaxDynamicSharedMemorySize, M3_SMEM);
        cudaFuncSetAttribute(k_lstm_mm, cudaFuncAttributeMaxDynamicSharedMemorySize, LSTM_SMEM);
        attr_done = true;
    }

    dim3 gmlp(NBLK, T_);
    k_mlp1<<<gmlp, 256>>>(x, W1, b1, g1, be1, Wih, Whh);
    k_mlp2<<<gmlp, 256>>>(W2, b2, g2, be2);
    k_mlp3<<<NBLK, 256, M3_SMEM>>>(W3, b3, bih, bhh);
    k_lstm_mm<<<148, 448, LSTM_SMEM>>>(bih, bhh, out);
}

// round 15
// speedup vs baseline: 1.8116x; 1.2225x over previous
#include <cuda_runtime.h>
#include <cuda_bf16.h>
#include <cuda_fp16.h>
#include <cstdint>
#include <cstddef>

#define B_    32768
#define T_    3
#define D_    64
#define H_    32
#define NBLK  128   // B_/256

// ---------------- scratch (device globals: allocation-free) ----------------
__device__ unsigned long long g_xg[(size_t)T_ * 128 * B_]; // xg pairs [t][j/2][r]
__device__ float g_h1[(size_t)T_ * B_ * H_];
__device__ float g_h2[(size_t)T_ * B_ * H_];
__device__ float g_ps1[T_ * NBLK * H_];
__device__ float g_pq1[T_ * NBLK * H_];
__device__ float g_ps2[T_ * NBLK * H_];
__device__ float g_pq2[T_ * NBLK * H_];
__device__ float2 g_bn1[T_ * H_];   // (scale, shift)
__device__ float2 g_bn2[T_ * H_];
__device__ int g_c1[T_];            // last-block counters (self-resetting)
__device__ int g_c2[T_];
// weight tiles: 3 x [256 n][64 k] fp16, 128B rows, SW128-swizzled
// 0 = Whh fp16, 1 = (Wih+Whh) fp16, 2 = Wih fp16
__device__ __align__(16) uint8_t g_wt[3 * 32768];

#define UNPK(v, lo, hi) do { unsigned _l, _h; \
    asm("mov.b64 {%0,%1}, %2;" : "=r"(_l), "=r"(_h) : "l"(v)); \
    lo = __uint_as_float(_l); hi = __uint_as_float(_h); } while (0)
#define PK64(lo, hi, v) asm("mov.b64 %0, {%1,%2};" : "=l"(v) : "r"(__float_as_uint(lo)), "r"(__float_as_uint(hi)))
// packed fp32x2 FMA (bit-identical to two fmaf)
#define FMA2(a, b, c) asm("fma.rn.f32x2 %0, %1, %2, %0;" : "+l"(a) : "l"(b), "l"(c))
#define BCAST2(v, x) asm("mov.b64 %0, {%1,%1};" : "=l"(v) : "r"(__float_as_uint(x)))

__device__ __forceinline__ float ex2f(float x) {
    float r; asm("ex2.approx.ftz.f32 %0, %1;" : "=f"(r) : "f"(x)); return r;
}
__device__ __forceinline__ float rcpf(float x) {
    float r; asm("rcp.approx.ftz.f32 %0, %1;" : "=f"(r) : "f"(x)); return r;
}
// paired LSTM cells: shares RCPs between the two cells. 12 MUFU / pair.
__device__ __forceinline__ void lstm_cell2(float gi0, float gf0, float gg0, float go0,
                                           float gi1, float gf1, float gg1, float go1,
                                           float& c0, float& c1, float& h0, float& h1) {
    const float L2E = 1.4426950408889634f;
    float a0 = ex2f(-L2E * gf0), u0 = ex2f(-L2E * gi0), b0 = ex2f(-2.f * L2E * gg0);
    float a1 = ex2f(-L2E * gf1), u1 = ex2f(-L2E * gi1), b1 = ex2f(-2.f * L2E * gg1);
    float pa0 = 1.f + a0, t0 = (1.f + u0) * (1.f + b0);
    float pa1 = 1.f + a1, t1 = (1.f + u1) * (1.f + b1);
    float D0 = pa0 * t0, N0 = c0 * t0 + (1.f - b0) * pa0;
    float D1 = pa1 * t1, N1 = c1 * t1 + (1.f - b1) * pa1;
    float r = rcpf(D0 * D1);
    float cn0 = N0 * (r * D1), cn1 = N1 * (r * D0);
    float v0 = ex2f(-L2E * go0), w0 = ex2f(-2.f * L2E * cn0);
    float v1 = ex2f(-L2E * go1), w1 = ex2f(-2.f * L2E * cn1);
    float P0 = (1.f + v0) * (1.f + w0), P1 = (1.f + v1) * (1.f + w1);
    float r2 = rcpf(P0 * P1);
    c0 = cn0; c1 = cn1;
    h0 = (1.f - w0) * (r2 * P1);
    h1 = (1.f - w1) * (r2 * P0);
}
__host__ __device__ __forceinline__ uint32_t swz128(uint32_t o) {
    return o ^ ((o >> 3) & 0x70);
}
__device__ __forceinline__ uint32_t pack_f16(float lo, float hi) {
    __half2 h2v = __floats2half2_rn(lo, hi);
    return *(uint32_t*)&h2v;
}

// ---------------- stage 1: h1 = x @ W1^T + b1, + fused BN1 stats + weight prep ----------------
__global__ void __launch_bounds__(256) k_mlp1(const float* __restrict__ x,
                                              const float* __restrict__ W1,
                                              const float* __restrict__ b1,
                                              const float* __restrict__ g1,
                                              const float* __restrict__ be1,
                                              const float* __restrict__ Wih,
                                              const float* __restrict__ Whh) {
    __shared__ __align__(16) float sW[D_ * H_];
    __shared__ float sacc[256 * 33];
    __shared__ float sr0[8 * 32], sr1[8 * 32];
    __shared__ int sflag;
    int tid = threadIdx.x;
    int t = blockIdx.y;
    int r = blockIdx.x * 256 + tid;
    for (int i = tid; i < D_ * H_; i += 256) { int j = i >> 6, k = i & 63; sW[k * H_ + j] = W1[i]; }
    __syncthreads();

    float xr[64];
    const float4* xp = (const float4*)(x + ((size_t)t * B_ + r) * D_);
#pragma unroll
    for (int i = 0; i < 16; i++) {
        float4 v = xp[i];
        xr[4*i] = v.x; xr[4*i+1] = v.y; xr[4*i+2] = v.z; xr[4*i+3] = v.w;
    }
    float acc[32];
    {
        unsigned long long acc2[16];
#pragma unroll
        for (int j = 0; j < 16; j++) acc2[j] = *(const unsigned long long*)&b1[2 * j];
#pragma unroll
        for (int k = 0; k < 64; k++) {
            unsigned long long xk2;
            BCAST2(xk2, xr[k]);
            const ulonglong2* wv = (const ulonglong2*)&sW[k * H_];
#pragma unroll
            for (int q = 0; q < 8; q++) {
                ulonglong2 w = wv[q];
                FMA2(acc2[2*q],   w.x, xk2);
                FMA2(acc2[2*q+1], w.y, xk2);
            }
        }
#pragma unroll
        for (int j = 0; j < 16; j++) UNPK(acc2[j], acc[2*j], acc[2*j+1]);
    }
    float4* op = (float4*)(g_h1 + ((size_t)t * B_ + r) * H_);
#pragma unroll
    for (int q = 0; q < 8; q++) op[q] = make_float4(acc[q*4], acc[q*4+1], acc[q*4+2], acc[q*4+3]);

    // smem transpose reduction for batch stats
#pragma unroll
    for (int j = 0; j < 32; j++) sacc[tid * 33 + j] = acc[j];
    __syncthreads();
    int part = tid >> 5, ch = tid & 31;
    {
        float s = 0.f, q = 0.f;
#pragma unroll
        for (int rr = 0; rr < 32; rr++) {
            float v = sacc[(part * 32 + rr) * 33 + ch];
            s += v; q = fmaf(v, v, q);
        }
        sr0[part * 32 + ch] = s;
        sr1[part * 32 + ch] = q;
    }
    __syncthreads();
    if (tid < 32) {
        float s = 0.f, q = 0.f;
#pragma unroll
        for (int p = 0; p < 8; p++) { s += sr0[p * 32 + tid]; q += sr1[p * 32 + tid]; }
        g_ps1[(t * NBLK + blockIdx.x) * 32 + tid] = s;
        g_pq1[(t * NBLK + blockIdx.x) * 32 + tid] = q;
    }

    // fused weight prep (fp16 tiles), frame-0 blocks 0..63 only
    if (t == 0 && blockIdx.x < 64) {
        int idx = blockIdx.x * 256 + tid;   // < 16384
        int n = idx >> 6, k = idx & 63;
        float whh = Whh[idx];
        float wih = Wih[idx];
        uint32_t off = swz128((uint32_t)(n * 128 + k * 2));
        *(__half*)(g_wt + 0 * 32768 + off) = __float2half_rn(whh);
        *(__half*)(g_wt + 1 * 32768 + off) = __float2half_rn(whh + wih);
        *(__half*)(g_wt + 2 * 32768 + off) = __float2half_rn(wih);
    }

    // last block per frame computes BN scale/shift
    __syncthreads();
    __threadfence();
    if (tid == 0) sflag = (atomicAdd(&g_c1[t], 1) == NBLK - 1);
    __syncthreads();
    if (sflag) {
        __threadfence();
        float s = 0.f, q = 0.f;
        for (int b = part; b < NBLK; b += 8) {
            s += g_ps1[(t * NBLK + b) * 32 + ch];
            q += g_pq1[(t * NBLK + b) * 32 + ch];
        }
        sr0[part * 32 + ch] = s;
        sr1[part * 32 + ch] = q;
        __syncthreads();
        if (tid < 32) {
            float s3 = 0.f, q3 = 0.f;
#pragma unroll
            for (int p = 0; p < 8; p++) { s3 += sr0[p * 32 + tid]; q3 += sr1[p * 32 + tid]; }
            float m = s3 * (1.f / B_);
            float v = q3 * (1.f / B_) - m * m;
            float sc = g1[tid] * rsqrtf(v + 1e-5f);
            g_bn1[t * 32 + tid] = make_float2(sc, be1[tid] - m * sc);
        }
        if (tid == 0) g_c1[t] = 0;   // reset for next graph replay
    }
}

// ---------------- stage 2: h2 = relu(BN1(h1)) @ W2^T + b2, + fused BN2 stats ----------------
__global__ void __launch_bounds__(256) k_mlp2(const float* __restrict__ W2,
                                              const float* __restrict__ b2,
                                              const float* __restrict__ g2,
                                              const float* __restrict__ be2) {
    __shared__ __align__(16) float sW[H_ * H_];
    __shared__ float sacc[256 * 33];
    __shared__ float sr0[8 * 32], sr1[8 * 32];
    __shared__ int sflag;
    int tid = threadIdx.x;
    int t = blockIdx.y;
    int r = blockIdx.x * 256 + tid;
    for (int i = tid; i < H_ * H_; i += 256) { int j = i >> 5, k = i & 31; sW[k * H_ + j] = W2[i]; }
    __syncthreads();

    float a[32];
    const float4* hp = (const float4*)(g_h1 + ((size_t)t * B_ + r) * H_);
#pragma unroll
    for (int i = 0; i < 8; i++) {
        float4 v = hp[i];
        float2 s0 = g_bn1[t * 32 + i * 4 + 0]; a[i*4+0] = fmaxf(0.f, fmaf(v.x, s0.x, s0.y));
        float2 s1 = g_bn1[t * 32 + i * 4 + 1]; a[i*4+1] = fmaxf(0.f, fmaf(v.y, s1.x, s1.y));
        float2 s2 = g_bn1[t * 32 + i * 4 + 2]; a[i*4+2] = fmaxf(0.f, fmaf(v.z, s2.x, s2.y));
        float2 s3 = g_bn1[t * 32 + i * 4 + 3]; a[i*4+3] = fmaxf(0.f, fmaf(v.w, s3.x, s3.y));
    }
    float acc[32];
    {
        unsigned long long acc2[16];
#pragma unroll
        for (int j = 0; j < 16; j++) acc2[j] = *(const unsigned long long*)&b2[2 * j];
#pragma unroll
        for (int k = 0; k < 32; k++) {
            unsigned long long ak2;
            BCAST2(ak2, a[k]);
            const ulonglong2* wv = (const ulonglong2*)&sW[k * H_];
#pragma unroll
            for (int q = 0; q < 8; q++) {
                ulonglong2 w = wv[q];
                FMA2(acc2[2*q],   w.x, ak2);
                FMA2(acc2[2*q+1], w.y, ak2);
            }
        }
#pragma unroll
        for (int j = 0; j < 16; j++) UNPK(acc2[j], acc[2*j], acc[2*j+1]);
    }
    float4* op = (float4*)(g_h2 + ((size_t)t * B_ + r) * H_);
#pragma unroll
    for (int q = 0; q < 8; q++) op[q] = make_float4(acc[q*4], acc[q*4+1], acc[q*4+2], acc[q*4+3]);

#pragma unroll
    for (int j = 0; j < 32; j++) sacc[tid * 33 + j] = acc[j];
    __syncthreads();
    int part = tid >> 5, ch = tid & 31;
    {
        float s = 0.f, q = 0.f;
#pragma unroll
        for (int rr = 0; rr < 32; rr++) {
            float v = sacc[(part * 32 + rr) * 33 + ch];
            s += v; q = fmaf(v, v, q);
        }
        sr0[part * 32 + ch] = s;
        sr1[part * 32 + ch] = q;
    }
    __syncthreads();
    if (tid < 32) {
        float s = 0.f, q = 0.f;
#pragma unroll
        for (int p = 0; p < 8; p++) { s += sr0[p * 32 + tid]; q += sr1[p * 32 + tid]; }
        g_ps2[(t * NBLK + blockIdx.x) * 32 + tid] = s;
        g_pq2[(t * NBLK + blockIdx.x) * 32 + tid] = q;
    }
    __syncthreads();
    __threadfence();
    if (tid == 0) sflag = (atomicAdd(&g_c2[t], 1) == NBLK - 1);
    __syncthreads();
    if (sflag) {
        __threadfence();
        float s = 0.f, q = 0.f;
        for (int b = part; b < NBLK; b += 8) {
            s += g_ps2[(t * NBLK + b) * 32 + ch];
            q += g_pq2[(t * NBLK + b) * 32 + ch];
        }
        sr0[part * 32 + ch] = s;
        sr1[part * 32 + ch] = q;
        __syncthreads();
        if (tid < 32) {
            float s3 = 0.f, q3 = 0.f;
#pragma unroll
            for (int p = 0; p < 8; p++) { s3 += sr0[p * 32 + tid]; q3 += sr1[p * 32 + tid]; }
            float m = s3 * (1.f / B_);
            float v = q3 * (1.f / B_) - m * m;
            float sc = g2[tid] * rsqrtf(v + 1e-5f);
            g_bn2[t * 32 + tid] = make_float2(sc, be2[tid] - m * sc);
        }
        if (tid == 0) g_c2[t] = 0;
    }
}

// ---------------- HMMA helpers ----------------
__device__ __forceinline__ void mma_f16(float d[4], const uint32_t a[4],
                                        uint32_t b0, uint32_t b1) {
    asm volatile(
        "mma.sync.aligned.m16n8k16.row.col.f32.f16.f16.f32 "
        "{%0,%1,%2,%3}, {%4,%5,%6,%7}, {%8,%9}, {%0,%1,%2,%3};"
        : "+f"(d[0]), "+f"(d[1]), "+f"(d[2]), "+f"(d[3])
        : "r"(a[0]), "r"(a[1]), "r"(a[2]), "r"(a[3]), "r"(b0), "r"(b1));
}
__device__ __forceinline__ void ldsm4(uint32_t r[4], uint32_t addr) {
    asm volatile("ldmatrix.sync.aligned.m8n8.x4.shared.b16 {%0,%1,%2,%3}, [%4];"
                 : "=r"(r[0]), "=r"(r[1]), "=r"(r[2]), "=r"(r[3]) : "r"(addr) : "memory");
}

// ---- stage 3: enc = relu(BN2(h2)) @ W3^T + b3; xg = enc @ Wih^T + bsum (fp16 2-term HMMA) ----
// smem: A_HI 32K @0, A_LO 32K @32768, WIH fp16 32K @65536, sW3 8K @98304, sb 1K @106496
#define M3_AHI 0u
#define M3_ALO 32768u
#define M3_WIH 65536u
#define M3_SW3 98304u
#define M3_SB  106496u
#define M3_SMEM 107520
__global__ void __launch_bounds__(256) k_mlp3(const float* __restrict__ W3,
                                              const float* __restrict__ b3,
                                              const float* __restrict__ bih,
                                              const float* __restrict__ bhh) {
    extern __shared__ __align__(16) uint8_t sm3[];
    uint32_t smem_base;
    asm("{ .reg .u64 t; cvta.to.shared.u64 t, %1; cvt.u32.u64 %0, t; }"
        : "=r"(smem_base) : "l"(sm3));
    float* sW3 = (float*)(sm3 + M3_SW3);
    float* sb  = (float*)(sm3 + M3_SB);
    const int tid = threadIdx.x, wid = tid >> 5, lane = tid & 31;

    for (int i = tid; i < 2048; i += 256) { int j = i >> 5, k = i & 31; sW3[k * 64 + j] = W3[i]; }
    {
        const uint4* src = (const uint4*)(g_wt + 2 * 32768);   // Wih fp16 (32KB)
        uint4* dst = (uint4*)(sm3 + M3_WIH);
        for (int i = tid; i < 32768 / 16; i += 256) dst[i] = src[i];
    }
    sb[tid] = bih[tid] + bhh[tid];
    __syncthreads();

    const int l7 = lane & 7;
    const uint32_t lxor = (uint32_t)l7 * 16u;
    const uint32_t aoff16 = (uint32_t)((lane >> 4) & 1) * 16u;
    const uint32_t boff16 = (uint32_t)((lane >> 3) & 1) * 16u;
    const uint32_t arow0 = (uint32_t)(wid * 32 + l7 + ((lane >> 3) & 1) * 8) * 128u;
    const uint32_t brow_l = (uint32_t)(((lane >> 4) & 1) * 8 + l7) * 128u;
    const int qr = lane >> 2, qc = lane & 3;
    const size_t rowG0 = (size_t)blockIdx.x * 256 + wid * 32 + qr;
    const uint32_t aHi = smem_base + M3_AHI, aLo = smem_base + M3_ALO;
    const uint32_t wih_s = smem_base + M3_WIH;

#pragma unroll 1
    for (int t = 0; t < T_; t++) {
        // phase 1: enc for own row (= tid)
        const size_t r = (size_t)blockIdx.x * 256 + tid;
        float a[32];
        const float4* hp = (const float4*)(g_h2 + ((size_t)t * B_ + r) * H_);
#pragma unroll
        for (int i = 0; i < 8; i++) {
            float4 v = hp[i];
            float2 s0 = g_bn2[t * 32 + i * 4 + 0]; a[i*4+0] = fmaxf(0.f, fmaf(v.x, s0.x, s0.y));
            float2 s1 = g_bn2[t * 32 + i * 4 + 1]; a[i*4+1] = fmaxf(0.f, fmaf(v.y, s1.x, s1.y));
            float2 s2 = g_bn2[t * 32 + i * 4 + 2]; a[i*4+2] = fmaxf(0.f, fmaf(v.z, s2.x, s2.y));
            float2 s3 = g_bn2[t * 32 + i * 4 + 3]; a[i*4+3] = fmaxf(0.f, fmaf(v.w, s3.x, s3.y));
        }
        float e[64];
        {
            unsigned long long e2[32];
#pragma unroll
            for (int j = 0; j < 32; j++) e2[j] = *(const unsigned long long*)&b3[2 * j];
#pragma unroll
            for (int k = 0; k < 32; k++) {
                unsigned long long ak2;
                BCAST2(ak2, a[k]);
                const ulonglong2* wv = (const ulonglong2*)&sW3[k * 64];
#pragma unroll
                for (int q = 0; q < 16; q++) {
                    ulonglong2 w = wv[q];
                    FMA2(e2[2*q],   w.x, ak2);
                    FMA2(e2[2*q+1], w.y, ak2);
                }
            }
#pragma unroll
            for (int j = 0; j < 32; j++) UNPK(e2[j], e[2*j], e[2*j+1]);
        }
        // split enc -> fp16 hi/lo A tiles (row = tid, SW128)
        {
            const uint32_t rb = (uint32_t)tid * 128u;
            const uint32_t rx = (uint32_t)(tid & 7) * 16u;
#pragma unroll
            for (int q = 0; q < 8; q++) {
                uint32_t off = rb + (((uint32_t)q * 16u) ^ rx);
                uint32_t ph[4], pl[4];
#pragma unroll
                for (int j = 0; j < 4; j++) {
                    float e0 = e[q*8 + 2*j], e1 = e[q*8 + 2*j + 1];
                    __half2 h2v = __floats2half2_rn(e0, e1);
                    ph[j] = *(uint32_t*)&h2v;
                    float r0 = e0 - __half2float(__low2half(h2v));
                    float r1 = e1 - __half2float(__high2half(h2v));
                    pl[j] = pack_f16(r0, r1);
                }
                *(uint4*)(sm3 + M3_AHI + off) = make_uint4(ph[0], ph[1], ph[2], ph[3]);
                *(uint4*)(sm3 + M3_ALO + off) = make_uint4(pl[0], pl[1], pl[2], pl[3]);
            }
        }
        __syncwarp();

        // phase 2: xg = enc @ Wih^T + bsum via fp16 HMMA (warp-private rows)
        unsigned long long* xgt = g_xg + (size_t)t * 128 * B_;
#pragma unroll
        for (int cd = 0; cd < 4; cd++) {
            float acc[2][4][2][4];
#pragma unroll
            for (int mt = 0; mt < 2; mt++)
#pragma unroll
                for (int g = 0; g < 4; g++)
#pragma unroll
                    for (int ds = 0; ds < 2; ds++)
#pragma unroll
                        for (int z = 0; z < 4; z++) acc[mt][g][ds][z] = 0.f;
            const uint32_t brow_cd = (uint32_t)(cd * 16) * 128u + brow_l;
#pragma unroll
            for (int kt = 0; kt < 4; kt++) {
                const uint32_t acol = ((uint32_t)(kt * 32) + aoff16) ^ lxor;
                const uint32_t bcol = ((uint32_t)(kt * 32) + boff16) ^ lxor;
                uint32_t ah[2][4], al[2][4];
                ldsm4(ah[0], aHi + arow0 + acol);
                ldsm4(ah[1], aHi + arow0 + 2048u + acol);
                ldsm4(al[0], aLo + arow0 + acol);
                ldsm4(al[1], aLo + arow0 + 2048u + acol);
                uint32_t wf[4][4];
#pragma unroll
                for (int g = 0; g < 4; g++)
                    ldsm4(wf[g], wih_s + (uint32_t)g * 8192u + brow_cd + bcol);
#pragma unroll
                for (int mt = 0; mt < 2; mt++)
#pragma unroll
                    for (int g = 0; g < 4; g++)
#pragma unroll
                        for (int ds = 0; ds < 2; ds++) {
                            mma_f16(acc[mt][g][ds], ah[mt], wf[g][ds*2], wf[g][ds*2+1]);
                            mma_f16(acc[mt][g][ds], al[mt], wf[g][ds*2], wf[g][ds*2+1]);
                        }
            }
#pragma unroll
            for (int g = 0; g < 4; g++)
#pragma unroll
                for (int ds = 0; ds < 2; ds++) {
                    const int pi = cd * 8 + ds * 4 + qc;
                    float2 bs = *(const float2*)&sb[g * 64 + 2 * pi];
#pragma unroll
                    for (int mt = 0; mt < 2; mt++)
#pragma unroll
                        for (int rr = 0; rr < 2; rr++) {
                            float v0 = acc[mt][g][ds][rr*2]     + bs.x;
                            float v1 = acc[mt][g][ds][rr*2 + 1] + bs.y;
                            unsigned long long pk;
                            PK64(v0, v1, pk);
                            xgt[(size_t)(g * 32 + pi) * B_ + rowG0 + mt * 16 + rr * 8] = pk;
                        }
                }
        }
        __syncwarp();
    }
}

// ---------------- stage 4: fp16 1-term HMMA 28-step LSTM, grid 148 x 448 ----------------
// smem: A dbl buffers 2x28672 (@0, @28672), W fp16 32KB @57344, bias @90112
#define LA_BUF   28672u
#define LW_OFF   57344u
#define LBIAS    90112u
#define LSTM_SMEM 91136

__global__ void __launch_bounds__(448, 1) k_lstm_mm(const float* __restrict__ bih,
                                                    const float* __restrict__ bhh,
                                                    float* __restrict__ out) {
    extern __shared__ __align__(16) uint8_t sm[];
    uint32_t smem_base;
    asm("{ .reg .u64 t; cvta.to.shared.u64 t, %1; cvt.u32.u64 %0, t; }"
        : "=r"(smem_base) : "l"(sm));
    float* sbsum = (float*)(sm + LBIAS);
    const int tid = threadIdx.x, wid = tid >> 5, lane = tid & 31;

    {   // Whh fp16 tile + biases
        const uint4* src = (const uint4*)g_wt;
        uint4* dst = (uint4*)(sm + LW_OFF);
        for (int i = tid; i < 32768 / 16; i += 448) dst[i] = src[i];
        if (tid < 256) sbsum[tid] = bih[tid] + bhh[tid];
    }
    __syncthreads();

    const int G = blockIdx.x + 148 * wid;          // 16-row group id
    const bool act = (G < 2048);
    const int l7 = lane & 7;
    const uint32_t lxor = (uint32_t)l7 * 16u;
    const uint32_t aoff16 = (uint32_t)((lane >> 4) & 1) * 16u;
    const uint32_t boff16 = (uint32_t)((lane >> 3) & 1) * 16u;
    const uint32_t arow0 = (uint32_t)(wid * 16 + l7 + ((lane >> 3) & 1) * 8) * 128u;
    const uint32_t brow_l = (uint32_t)(((lane >> 4) & 1) * 8 + l7) * 128u;
    const int qr = lane >> 2, qc = lane & 3;
    const int rowL0 = wid * 16 + qr;               // local A-tile row
    const size_t rowG0 = (size_t)G * 16 + qr;      // global row

    float c[32];
#pragma unroll
    for (int i = 0; i < 32; i++) c[i] = 0.f;

#pragma unroll 1
    for (int s = 0; s < 28; s++) {
        if (s == 4) {  // swap weights: Whh -> Wih+Whh (fp16)
            __syncthreads();
            const uint4* src = (const uint4*)(g_wt + 32768);
            uint4* dst = (uint4*)(sm + LW_OFF);
            for (int i = tid; i < 32768 / 16; i += 448) dst[i] = src[i];
            __syncthreads();
        }
        const uint32_t aRd = smem_base + (uint32_t)((s + 1) & 1) * LA_BUF;
        uint8_t* aWr = sm + (uint32_t)(s & 1) * LA_BUF;
        const uint32_t wBase = smem_base + LW_OFF;
        const int tsel = (s < 3) ? s : 2;
        const unsigned long long* xbase = g_xg + (size_t)tsel * 128 * B_;

#pragma unroll
        for (int cd = 0; cd < 4; cd++) {
            float acc[4][2][4];
#pragma unroll
            for (int g = 0; g < 4; g++)
#pragma unroll
                for (int ds = 0; ds < 2; ds++)
#pragma unroll
                    for (int z = 0; z < 4; z++) acc[g][ds][z] = 0.f;

            if (s >= 1) {
                const uint32_t brow_cd = (uint32_t)(cd * 16) * 128u + brow_l;
#pragma unroll
                for (int kt = 0; kt < 4; kt++) {
                    const uint32_t acol = ((uint32_t)(kt * 32) + aoff16) ^ lxor;
                    const uint32_t bcol = ((uint32_t)(kt * 32) + boff16) ^ lxor;
                    uint32_t ah[4];
                    ldsm4(ah, aRd + arow0 + acol);
                    uint32_t wf[4][4];
#pragma unroll
                    for (int g = 0; g < 4; g++)
                        ldsm4(wf[g], wBase + (uint32_t)g * 8192u + brow_cd + bcol);
#pragma unroll
                    for (int g = 0; g < 4; g++)
#pragma unroll
                        for (int ds = 0; ds < 2; ds++)
                            mma_f16(acc[g][ds], ah, wf[g][ds*2], wf[g][ds*2+1]);
                }
            }

            // epilogue for this 16-d chunk
            const int pbase = cd * 8 + qc;
#pragma unroll
            for (int ds = 0; ds < 2; ds++) {
                const int dbase = cd * 16 + ds * 8 + 2 * qc;
                float2 bi, bf, bg, bo;
                if (s >= 4) {
                    bi = *(const float2*)&sbsum[0 * 64 + dbase];
                    bf = *(const float2*)&sbsum[1 * 64 + dbase];
                    bg = *(const float2*)&sbsum[2 * 64 + dbase];
                    bo = *(const float2*)&sbsum[3 * 64 + dbase];
                }
#pragma unroll
                for (int rr = 0; rr < 2; rr++) {
                    const int rowL = rowL0 + rr * 8;
                    float gi0 = acc[0][ds][rr*2], gi1 = acc[0][ds][rr*2+1];
                    float gf0 = acc[1][ds][rr*2], gf1 = acc[1][ds][rr*2+1];
                    float gg0 = acc[2][ds][rr*2], gg1 = acc[2][ds][rr*2+1];
                    float go0 = acc[3][ds][rr*2], go1 = acc[3][ds][rr*2+1];
                    if (s < 4) {
                        const int pi = pbase + ds * 4;
                        float lo, hi;
                        unsigned long long v;
                        if (act) {
                            const unsigned long long* xp = xbase + (rowG0 + rr * 8);
                            v = xp[(size_t)(0 * 32 + pi) * B_]; UNPK(v, lo, hi); gi0 += lo; gi1 += hi;
                            v = xp[(size_t)(1 * 32 + pi) * B_]; UNPK(v, lo, hi); gf0 += lo; gf1 += hi;
                            v = xp[(size_t)(2 * 32 + pi) * B_]; UNPK(v, lo, hi); gg0 += lo; gg1 += hi;
                            v = xp[(size_t)(3 * 32 + pi) * B_]; UNPK(v, lo, hi); go0 += lo; go1 += hi;
                        }
                    } else {
                        gi0 += bi.x; gi1 += bi.y;
                        gf0 += bf.x; gf1 += bf.y;
                        gg0 += bg.x; gg1 += bg.y;
                        go0 += bo.x; go1 += bo.y;
                    }
                    const int ci = ((cd * 2 + ds) * 2 + rr) * 2;
                    float h0, h1;
                    lstm_cell2(gi0, gf0, gg0, go0, gi1, gf1, gg1, go1,
                               c[ci], c[ci + 1], h0, h1);
                    // pack h to fp16 (1-term) and store to next-step A tile
                    uint32_t ph = pack_f16(h0, h1);
                    uint32_t soff = (uint32_t)rowL * 128u +
                                    (((uint32_t)(cd * 32 + ds * 16 + qc * 4)) ^ ((uint32_t)qr * 16u));
                    *(uint32_t*)(aWr + soff) = ph;
                    if (s >= 3 && act) {
                        float2 o2 = make_float2(h0, h1);
                        *(float2*)(out + ((rowG0 + rr * 8) * 25 + (s - 3)) * 64 + dbase) = o2;
                    }
                }
            }
        }
        __syncwarp();
    }
}

// ---------------- host ----------------
extern "C" void kernel_launch(void* const* d_in, const int* in_sizes, int n_in,
                              void* d_out, int out_size) {
    const float* x   = (const float*)d_in[0];
    const float* W1  = (const float*)d_in[1];
    const float* b1  = (const float*)d_in[2];
    const float* g1  = (const float*)d_in[3];
    const float* be1 = (const float*)d_in[4];
    const float* W2  = (const float*)d_in[5];
    const float* b2  = (const float*)d_in[6];
    const float* g2  = (const float*)d_in[7];
    const float* be2 = (const float*)d_in[8];
    const float* W3  = (const float*)d_in[9];
    const float* b3  = (const float*)d_in[10];
    const float* Wih = (const float*)d_in[11];
    const float* Whh = (const float*)d_in[12];
    const float* bih = (const float*)d_in[13];
    const float* bhh = (const float*)d_in[14];
    float* out = (float*)d_out;

    static bool attr_done = false;
    if (!attr_done) {
        cudaFuncSetAttribute(k_mlp3, cudaFuncAttributeMaxDynamicSharedMemorySize, M3_SMEM);
        cudaFuncSetAttribute(k_lstm_mm, cudaFuncAttributeMaxDynamicSharedMemorySize, LSTM_SMEM);
        attr_done = true;
    }

    dim3 gmlp(NBLK, T_);
    k_mlp1<<<gmlp, 256>>>(x, W1, b1, g1, be1, Wih, Whh);
    k_mlp2<<<gmlp, 256>>>(W2, b2, g2, be2);
    k_mlp3<<<NBLK, 256, M3_SMEM>>>(W3, b3, bih, bhh);
    k_lstm_mm<<<148, 448, LSTM_SMEM>>>(bih, bhh, out);
}